// round 9
// baseline (speedup 1.0000x reference)
#include <cuda_runtime.h>
#include <cuda_bf16.h>
#include <math.h>

#define HW   16384
#define NPIX (8 * 16384)

// ---------------- scratch (device globals: no allocation allowed) ----------
__device__ float g_x[8 * 64 * HW];     // fused 1x1 conv output
__device__ float g_off[8 * 18 * HW];   // raw offset conv + bias
__device__ float g_mod[8 * 9 * HW];    // 2*sigmoid(conv + bias)

// ---------------- f32x2 packed helpers ------------------------------------
__device__ __forceinline__ unsigned long long pack2(float lo, float hi) {
    unsigned long long r;
    asm("mov.b64 %0, {%1, %2};" : "=l"(r) : "f"(lo), "f"(hi));
    return r;
}
__device__ __forceinline__ void unpack2(unsigned long long v, float& lo, float& hi) {
    asm("mov.b64 {%0, %1}, %2;" : "=f"(lo), "=f"(hi) : "l"(v));
}
__device__ __forceinline__ unsigned long long fma2(unsigned long long a,
                                                   unsigned long long b,
                                                   unsigned long long c) {
    unsigned long long d;
    asm("fma.rn.f32x2 %0, %1, %2, %3;" : "=l"(d) : "l"(a), "l"(b), "l"(c));
    return d;
}

// ===========================================================================
// Kernel 1: fused 1x1 conv (R6/R8 version — proven 78us).  UNCHANGED.
// ===========================================================================
__global__ void __launch_bounds__(256, 2)
k1_fuse(const float* __restrict__ x_img,
        const float* __restrict__ x_cont,
        const float* __restrict__ w_fuse) {
    extern __shared__ float s_wf[];                 // 128*64 fl = 32KB
    for (int idx = threadIdx.x; idx < 128 * 64; idx += blockDim.x) {
        int c = idx >> 6, o = idx & 63;
        s_wf[idx] = w_fuse[o * 128 + c];
    }
    __syncthreads();

    int t = threadIdx.x;
    int g = t >> 6;                                  // output group 0..3
    int q = blockIdx.x * 64 + (t & 63);              // pixel-quad index
    int b  = q >> 12;
    int hw = (q & 4095) << 2;

    const float* xi = x_img  + (size_t)b * 64 * HW + hw;
    const float* xc = x_cont + (size_t)b * 64 * HW + hw;

    unsigned long long acc[32];                      // acc[o*2 + pp]
#pragma unroll
    for (int m = 0; m < 32; m++) acc[m] = 0ULL;

    const float* wgrp = s_wf + g * 16;

#pragma unroll 1
    for (int c = 0; c < 64; c += 8) {
        float4 xv[8];
#pragma unroll
        for (int u = 0; u < 8; u++)
            xv[u] = *(const float4*)(xi + (size_t)(c + u) * HW);
#pragma unroll
        for (int u = 0; u < 8; u++) {
            unsigned long long s01 = pack2(xv[u].x, xv[u].y);
            unsigned long long s23 = pack2(xv[u].z, xv[u].w);
            const float4* wrow = (const float4*)(wgrp + (c + u) * 64);
#pragma unroll
            for (int j = 0; j < 4; j++) {
                float4 w4 = wrow[j];
                float we[4] = {w4.x, w4.y, w4.z, w4.w};
#pragma unroll
                for (int e = 0; e < 4; e++) {
                    unsigned long long wd = pack2(we[e], we[e]);
                    int o = j * 4 + e;
                    acc[o * 2 + 0] = fma2(wd, s01, acc[o * 2 + 0]);
                    acc[o * 2 + 1] = fma2(wd, s23, acc[o * 2 + 1]);
                }
            }
        }
    }
#pragma unroll 1
    for (int c = 0; c < 64; c += 8) {
        float4 xv[8];
#pragma unroll
        for (int u = 0; u < 8; u++)
            xv[u] = *(const float4*)(xc + (size_t)(c + u) * HW);
#pragma unroll
        for (int u = 0; u < 8; u++) {
            unsigned long long s01 = pack2(xv[u].x, xv[u].y);
            unsigned long long s23 = pack2(xv[u].z, xv[u].w);
            const float4* wrow = (const float4*)(wgrp + (64 + c + u) * 64);
#pragma unroll
            for (int j = 0; j < 4; j++) {
                float4 w4 = wrow[j];
                float we[4] = {w4.x, w4.y, w4.z, w4.w};
#pragma unroll
                for (int e = 0; e < 4; e++) {
                    unsigned long long wd = pack2(we[e], we[e]);
                    int o = j * 4 + e;
                    acc[o * 2 + 0] = fma2(wd, s01, acc[o * 2 + 0]);
                    acc[o * 2 + 1] = fma2(wd, s23, acc[o * 2 + 1]);
                }
            }
        }
    }

    float* op = g_x + (size_t)b * 64 * HW + hw;
#pragma unroll
    for (int o = 0; o < 16; o++) {
        float p0, p1, p2, p3;
        unpack2(acc[o * 2 + 0], p0, p1);
        unpack2(acc[o * 2 + 1], p2, p3);
        *(float4*)(op + (size_t)(g * 16 + o) * HW) = make_float4(p0, p1, p2, p3);
    }
}

// ===========================================================================
// Kernel 2: 3x3 conv -> 18 offsets (+bias) and 9 mod.  UNCHANGED.
// ===========================================================================
__global__ void __launch_bounds__(256, 2)
k2_offmod(const float* __restrict__ w_off,
          const float* __restrict__ w_mod,
          const float* __restrict__ b_off,
          const float* __restrict__ b_mod) {
    extern __shared__ unsigned long long s_w[];     // 64*9*14 u64 = 63KB
    float* s_wf = (float*)s_w;
    for (int idx = threadIdx.x; idx < 64 * 9 * 28; idx += blockDim.x) {
        int c = idx / 252;
        int r = idx % 252;
        int t = r / 28;
        int j = r % 28;
        float v;
        if (j < 18)       v = w_off[((size_t)j * 64 + c) * 9 + t];
        else if (j < 27)  v = w_mod[((size_t)(j - 18) * 64 + c) * 9 + t];
        else              v = 0.0f;
        s_wf[idx] = v;
    }
    __syncthreads();

    int pp = blockIdx.x * blockDim.x + threadIdx.x;  // pixel-pair index
    int b  = pp >> 13;
    int hw = (pp << 1) & 16383;
    int h  = hw >> 7;
    int w0 = hw & 127;                               // even

    int  offs[9];
    bool ok0[9], ok1[9];
#pragma unroll
    for (int t9 = 0; t9 < 9; t9++) {
        int ty = t9 / 3 - 1, tx = t9 % 3 - 1;
        int yy  = h + ty;
        int xx0 = w0 + tx;
        bool rowok = (unsigned)yy < 128u;
        ok0[t9] = rowok && ((unsigned)xx0 < 128u);
        ok1[t9] = rowok && ((unsigned)(xx0 + 1) < 128u);
        offs[t9] = yy * 128 + xx0;
    }

    unsigned long long acc[28];
#pragma unroll
    for (int m = 0; m < 28; m++) acc[m] = 0ULL;

    const float* xb0 = g_x + (size_t)b * 64 * HW;

#pragma unroll 1
    for (int c = 0; c < 64; c++) {
        const float* xb = xb0 + (size_t)c * HW;
#pragma unroll
        for (int t9 = 0; t9 < 9; t9++) {
            float v0 = ok0[t9] ? xb[offs[t9]]     : 0.0f;
            float v1 = ok1[t9] ? xb[offs[t9] + 1] : 0.0f;
            unsigned long long xp0 = pack2(v0, v0);
            unsigned long long xp1 = pack2(v1, v1);
            const unsigned long long* wrow = s_w + (c * 9 + t9) * 14;
#pragma unroll
            for (int jj = 0; jj < 14; jj += 2) {
                ulonglong2 wv = *(const ulonglong2*)(wrow + jj);
                acc[2 * jj + 0]       = fma2(wv.x, xp0, acc[2 * jj + 0]);
                acc[2 * jj + 1]       = fma2(wv.x, xp1, acc[2 * jj + 1]);
                acc[2 * (jj + 1) + 0] = fma2(wv.y, xp0, acc[2 * (jj + 1) + 0]);
                acc[2 * (jj + 1) + 1] = fma2(wv.y, xp1, acc[2 * (jj + 1) + 1]);
            }
        }
    }

    float e0[28], e1[28];
#pragma unroll
    for (int jj = 0; jj < 14; jj++) {
        float a, bb;
        unpack2(acc[2 * jj + 0], a, bb);  e0[2 * jj] = a;  e0[2 * jj + 1] = bb;
        unpack2(acc[2 * jj + 1], a, bb);  e1[2 * jj] = a;  e1[2 * jj + 1] = bb;
    }

#pragma unroll
    for (int j = 0; j < 18; j++) {
        float bo = b_off[j];
        *(unsigned long long*)(g_off + ((size_t)b * 18 + j) * HW + hw)
            = pack2(e0[j] + bo, e1[j] + bo);
    }
#pragma unroll
    for (int j = 0; j < 9; j++) {
        float bm = b_mod[j];
        float m0 = 2.0f / (1.0f + __expf(-(e0[18 + j] + bm)));
        float m1 = 2.0f / (1.0f + __expf(-(e1[18 + j] + bm)));
        *(unsigned long long*)(g_mod + ((size_t)b * 9 + j) * HW + hw)
            = pack2(m0, m1);
    }
}

// ===========================================================================
// Kernel 3 (REWRITE): two-phase smem-staged deformable conv.
// CTA = 256 threads, 256-pixel tile.  Per tap k:
//   phase A: thread tid samples pixel px=tid for all 64 ch -> s_samp[64][256]
//            (gathers done ONCE per pixel); coop-load tap weights dup'd (w,w)
//   phase B: 8 outs x 8 px register tile; per ch: 4 broadcast LDS.128 (w) +
//            2 contiguous LDS.128 (samples) + 32 FFMA2, zero packs.
// smem: s_samp 64KB + wdup 32KB = 96KB -> 2 CTAs/SM.
// ===========================================================================
__global__ void __launch_bounds__(256, 2)
k3_deform(const float* __restrict__ w_reg,
          float* __restrict__ out) {
    extern __shared__ float smem[];
    float* s_samp = smem;                                   // [64][256] floats
    unsigned long long* s_wd = (unsigned long long*)(smem + 64 * 256); // [64ch][64out]
    const unsigned long long* s_samp_u64 = (const unsigned long long*)s_samp;

    int tid = threadIdx.x;
    int b       = blockIdx.x >> 6;                  // 64 CTAs per batch image
    int hw_base = (blockIdx.x & 63) << 8;           // 256-px tile

    // this thread's sampled pixel
    int px = tid;
    int hw = hw_base + px;
    int h  = hw >> 7;
    int w  = hw & 127;

    const float* xb   = g_x   + (size_t)b * 64 * HW;
    const float* offp = g_off + (size_t)b * 18 * HW + hw;
    const float* modp = g_mod + (size_t)b * 9 * HW + hw;

    // GEMM tile coords
    int ty = tid >> 5;                               // out group: outs ty*8..+8
    int tx = tid & 31;                               // px chunks tx*4, 128+tx*4

    unsigned long long acc[8][4];                    // [out][pxpair] over 9 taps
#pragma unroll
    for (int o = 0; o < 8; o++)
#pragma unroll
        for (int q = 0; q < 4; q++) acc[o][q] = 0ULL;

#pragma unroll 1
    for (int k = 0; k < 9; k++) {
        __syncthreads();   // previous tap's GEMM reads done before overwrite

        // ---- phase A.1: cooperative weight load for tap k (dup'd) ----
#pragma unroll 1
        for (int idx = tid; idx < 64 * 64; idx += 256) {
            int ch = idx >> 6, o = idx & 63;
            float wv = w_reg[(size_t)o * 576 + ch * 9 + k];
            s_wd[idx] = pack2(wv, wv);
        }

        // ---- phase A.2: sample pixel px for all 64 channels ----
        {
            int ky = k / 3, kx = k % 3;
            float dy = offp[(size_t)(2 * k) * HW];
            float dx = offp[(size_t)(2 * k + 1) * HW];
            float mk = modp[(size_t)k * HW];

            float py  = dy + (float)(h - 1 + ky);
            float pxx = dx + (float)(w - 1 + kx);
            float y0f = floorf(py), x0f = floorf(pxx);
            float wy1 = py - y0f, wy0 = 1.0f - wy1;
            float wx1 = pxx - x0f, wx0 = 1.0f - wx1;
            int y0 = (int)y0f, x0 = (int)x0f;
            int y1 = y0 + 1,   x1 = x0 + 1;
            bool vy0 = (unsigned)y0 < 128u, vy1 = (unsigned)y1 < 128u;
            bool vx0 = (unsigned)x0 < 128u, vx1 = (unsigned)x1 < 128u;
            float w00 = (vy0 && vx0) ? wy0 * wx0 * mk : 0.0f;
            float w01 = (vy0 && vx1) ? wy0 * wx1 * mk : 0.0f;
            float w10 = (vy1 && vx0) ? wy1 * wx0 * mk : 0.0f;
            float w11 = (vy1 && vx1) ? wy1 * wx1 * mk : 0.0f;
            int y0c = min(max(y0, 0), 127), y1c = min(max(y1, 0), 127);
            int x0c = min(max(x0, 0), 127), x1c = min(max(x1, 0), 127);
            int a00 = y0c * 128 + x0c;
            int a01 = y0c * 128 + x1c;
            int a10 = y1c * 128 + x0c;
            int a11 = y1c * 128 + x1c;

#pragma unroll 1
            for (int c0 = 0; c0 < 64; c0 += 4) {
                float v[16];
#pragma unroll
                for (int u = 0; u < 4; u++) {
                    const float* pi = xb + (size_t)(c0 + u) * HW;
                    v[4 * u + 0] = pi[a00];
                    v[4 * u + 1] = pi[a01];
                    v[4 * u + 2] = pi[a10];
                    v[4 * u + 3] = pi[a11];
                }
#pragma unroll
                for (int u = 0; u < 4; u++) {
                    float s = v[4 * u + 0] * w00;
                    s = fmaf(v[4 * u + 1], w01, s);
                    s = fmaf(v[4 * u + 2], w10, s);
                    s = fmaf(v[4 * u + 3], w11, s);
                    s_samp[(c0 + u) * 256 + px] = s;
                }
            }
        }

        __syncthreads();

        // ---- phase B: GEMM accumulate (8 outs x 8 px per thread) ----
#pragma unroll 1
        for (int ch = 0; ch < 64; ch++) {
            const ulonglong2* wrow = (const ulonglong2*)(s_wd + ch * 64 + ty * 8);
            ulonglong2 w01v = wrow[0];
            ulonglong2 w23v = wrow[1];
            ulonglong2 w45v = wrow[2];
            ulonglong2 w67v = wrow[3];
            unsigned long long wv[8] = {w01v.x, w01v.y, w23v.x, w23v.y,
                                        w45v.x, w45v.y, w67v.x, w67v.y};
            ulonglong2 sA = *(const ulonglong2*)(s_samp_u64 + ch * 128 + tx * 2);
            ulonglong2 sB = *(const ulonglong2*)(s_samp_u64 + ch * 128 + 64 + tx * 2);
#pragma unroll
            for (int o = 0; o < 8; o++) {
                acc[o][0] = fma2(wv[o], sA.x, acc[o][0]);
                acc[o][1] = fma2(wv[o], sA.y, acc[o][1]);
                acc[o][2] = fma2(wv[o], sB.x, acc[o][2]);
                acc[o][3] = fma2(wv[o], sB.y, acc[o][3]);
            }
        }
    }

    // ---- output: 8 outs x (2 chunks of 4 px) ----
    float* ob = out + ((size_t)b * 64 + ty * 8) * HW + hw_base;
#pragma unroll
    for (int o = 0; o < 8; o++) {
        float p0, p1, p2, p3;
        unpack2(acc[o][0], p0, p1);
        unpack2(acc[o][1], p2, p3);
        *(float4*)(ob + (size_t)o * HW + tx * 4) = make_float4(p0, p1, p2, p3);
        unpack2(acc[o][2], p0, p1);
        unpack2(acc[o][3], p2, p3);
        *(float4*)(ob + (size_t)o * HW + 128 + tx * 4) = make_float4(p0, p1, p2, p3);
    }
}

// ===========================================================================
extern "C" void kernel_launch(void* const* d_in, const int* in_sizes, int n_in,
                              void* d_out, int out_size) {
    const float* x_img  = (const float*)d_in[0];
    const float* x_cont = (const float*)d_in[1];
    const float* w_fuse = (const float*)d_in[2];
    const float* w_off  = (const float*)d_in[3];
    const float* b_off  = (const float*)d_in[4];
    const float* w_mod  = (const float*)d_in[5];
    const float* b_mod  = (const float*)d_in[6];
    const float* w_reg  = (const float*)d_in[7];
    float* out = (float*)d_out;

    const int K3_SMEM = 64 * 256 * 4 + 64 * 64 * 8;   // 96KB

    cudaFuncSetAttribute(k2_offmod,
                         cudaFuncAttributeMaxDynamicSharedMemorySize, 64 * 9 * 14 * 8);
    cudaFuncSetAttribute(k3_deform,
                         cudaFuncAttributeMaxDynamicSharedMemorySize, K3_SMEM);

    // k1: 512 blocks x 256 thr; thread = (pixel-quad, out-group of 16)
    k1_fuse<<<512, 256, 128 * 64 * 4>>>(x_img, x_cont, w_fuse);
    // k2: 256 blocks x 256 thr; thread = pixel-pair
    k2_offmod<<<(NPIX / 2) / 256, 256, 64 * 9 * 14 * 8>>>(w_off, w_mod, b_off, b_mod);
    // k3: 512 blocks x 256 thr; CTA = 256-pixel tile, all 64 outputs
    k3_deform<<<512, 256, K3_SMEM>>>(w_reg, out);
}

// round 11
// speedup vs baseline: 1.3807x; 1.3807x over previous
#include <cuda_runtime.h>
#include <cuda_bf16.h>
#include <math.h>

#define HW   16384
#define NPIX (8 * 16384)

// ---------------- scratch (device globals: no allocation allowed) ----------
__device__ float g_x[8 * 64 * HW];     // fused 1x1 conv output
__device__ float g_off[8 * 18 * HW];   // raw offset conv + bias
__device__ float g_mod[8 * 9 * HW];    // 2*sigmoid(conv + bias)

// ---------------- f32x2 packed helpers ------------------------------------
__device__ __forceinline__ unsigned long long pack2(float lo, float hi) {
    unsigned long long r;
    asm("mov.b64 %0, {%1, %2};" : "=l"(r) : "f"(lo), "f"(hi));
    return r;
}
__device__ __forceinline__ void unpack2(unsigned long long v, float& lo, float& hi) {
    asm("mov.b64 {%0, %1}, %2;" : "=f"(lo), "=f"(hi) : "l"(v));
}
__device__ __forceinline__ unsigned long long fma2(unsigned long long a,
                                                   unsigned long long b,
                                                   unsigned long long c) {
    unsigned long long d;
    asm("fma.rn.f32x2 %0, %1, %2, %3;" : "=l"(d) : "l"(a), "l"(b), "l"(c));
    return d;
}

// ---------------- mma.sync helpers (sm_80+ baseline, legal on sm_103) ------
__device__ __forceinline__ unsigned smem_u32(const void* p) {
    unsigned a;
    asm("{ .reg .u64 t; cvta.to.shared.u64 t, %1; cvt.u32.u64 %0, t; }"
        : "=r"(a) : "l"(p));
    return a;
}
__device__ __forceinline__ unsigned lds32(unsigned a) {
    unsigned v;
    asm("ld.shared.b32 %0, [%1];" : "=r"(v) : "r"(a));
    return v;
}
__device__ __forceinline__ void sts32(unsigned a, unsigned v) {
    asm volatile("st.shared.b32 [%0], %1;" :: "r"(a), "r"(v) : "memory");
}
__device__ __forceinline__ void mma16816(float* d, const unsigned* a,
                                         unsigned b0, unsigned b1) {
    asm volatile(
        "mma.sync.aligned.m16n8k16.row.col.f32.bf16.bf16.f32 "
        "{%0,%1,%2,%3}, {%4,%5,%6,%7}, {%8,%9}, {%0,%1,%2,%3};"
        : "+f"(d[0]), "+f"(d[1]), "+f"(d[2]), "+f"(d[3])
        : "r"(a[0]), "r"(a[1]), "r"(a[2]), "r"(a[3]), "r"(b0), "r"(b1));
}
// split (a,b) into bf16 hi pair + bf16 lo (residual) pair, packed u32
__device__ __forceinline__ void split_pair(float a, float b,
                                           unsigned& hi, unsigned& lo) {
    __nv_bfloat16 ah = __float2bfloat16(a);
    __nv_bfloat16 bh = __float2bfloat16(b);
    __nv_bfloat16 al = __float2bfloat16(a - __bfloat162float(ah));
    __nv_bfloat16 bl = __float2bfloat16(b - __bfloat162float(bh));
    hi = (unsigned)__bfloat16_as_ushort(ah) | ((unsigned)__bfloat16_as_ushort(bh) << 16);
    lo = (unsigned)__bfloat16_as_ushort(al) | ((unsigned)__bfloat16_as_ushort(bl) << 16);
}

// ===========================================================================
// Kernel 1: fused 1x1 conv (proven 78us).  UNCHANGED.
// ===========================================================================
__global__ void __launch_bounds__(256, 2)
k1_fuse(const float* __restrict__ x_img,
        const float* __restrict__ x_cont,
        const float* __restrict__ w_fuse) {
    extern __shared__ float s_wf[];                 // 128*64 fl = 32KB
    for (int idx = threadIdx.x; idx < 128 * 64; idx += blockDim.x) {
        int c = idx >> 6, o = idx & 63;
        s_wf[idx] = w_fuse[o * 128 + c];
    }
    __syncthreads();

    int t = threadIdx.x;
    int g = t >> 6;
    int q = blockIdx.x * 64 + (t & 63);
    int b  = q >> 12;
    int hw = (q & 4095) << 2;

    const float* xi = x_img  + (size_t)b * 64 * HW + hw;
    const float* xc = x_cont + (size_t)b * 64 * HW + hw;

    unsigned long long acc[32];
#pragma unroll
    for (int m = 0; m < 32; m++) acc[m] = 0ULL;

    const float* wgrp = s_wf + g * 16;

#pragma unroll 1
    for (int c = 0; c < 64; c += 8) {
        float4 xv[8];
#pragma unroll
        for (int u = 0; u < 8; u++)
            xv[u] = *(const float4*)(xi + (size_t)(c + u) * HW);
#pragma unroll
        for (int u = 0; u < 8; u++) {
            unsigned long long s01 = pack2(xv[u].x, xv[u].y);
            unsigned long long s23 = pack2(xv[u].z, xv[u].w);
            const float4* wrow = (const float4*)(wgrp + (c + u) * 64);
#pragma unroll
            for (int j = 0; j < 4; j++) {
                float4 w4 = wrow[j];
                float we[4] = {w4.x, w4.y, w4.z, w4.w};
#pragma unroll
                for (int e = 0; e < 4; e++) {
                    unsigned long long wd = pack2(we[e], we[e]);
                    int o = j * 4 + e;
                    acc[o * 2 + 0] = fma2(wd, s01, acc[o * 2 + 0]);
                    acc[o * 2 + 1] = fma2(wd, s23, acc[o * 2 + 1]);
                }
            }
        }
    }
#pragma unroll 1
    for (int c = 0; c < 64; c += 8) {
        float4 xv[8];
#pragma unroll
        for (int u = 0; u < 8; u++)
            xv[u] = *(const float4*)(xc + (size_t)(c + u) * HW);
#pragma unroll
        for (int u = 0; u < 8; u++) {
            unsigned long long s01 = pack2(xv[u].x, xv[u].y);
            unsigned long long s23 = pack2(xv[u].z, xv[u].w);
            const float4* wrow = (const float4*)(wgrp + (64 + c + u) * 64);
#pragma unroll
            for (int j = 0; j < 4; j++) {
                float4 w4 = wrow[j];
                float we[4] = {w4.x, w4.y, w4.z, w4.w};
#pragma unroll
                for (int e = 0; e < 4; e++) {
                    unsigned long long wd = pack2(we[e], we[e]);
                    int o = j * 4 + e;
                    acc[o * 2 + 0] = fma2(wd, s01, acc[o * 2 + 0]);
                    acc[o * 2 + 1] = fma2(wd, s23, acc[o * 2 + 1]);
                }
            }
        }
    }

    float* op = g_x + (size_t)b * 64 * HW + hw;
#pragma unroll
    for (int o = 0; o < 16; o++) {
        float p0, p1, p2, p3;
        unpack2(acc[o * 2 + 0], p0, p1);
        unpack2(acc[o * 2 + 1], p2, p3);
        *(float4*)(op + (size_t)(g * 16 + o) * HW) = make_float4(p0, p1, p2, p3);
    }
}

// ===========================================================================
// Kernel 2: 3x3 conv -> offsets/mod.  UNCHANGED.
// ===========================================================================
__global__ void __launch_bounds__(256, 2)
k2_offmod(const float* __restrict__ w_off,
          const float* __restrict__ w_mod,
          const float* __restrict__ b_off,
          const float* __restrict__ b_mod) {
    extern __shared__ unsigned long long s_w[];     // 64*9*14 u64 = 63KB
    float* s_wf = (float*)s_w;
    for (int idx = threadIdx.x; idx < 64 * 9 * 28; idx += blockDim.x) {
        int c = idx / 252;
        int r = idx % 252;
        int t = r / 28;
        int j = r % 28;
        float v;
        if (j < 18)       v = w_off[((size_t)j * 64 + c) * 9 + t];
        else if (j < 27)  v = w_mod[((size_t)(j - 18) * 64 + c) * 9 + t];
        else              v = 0.0f;
        s_wf[idx] = v;
    }
    __syncthreads();

    int pp = blockIdx.x * blockDim.x + threadIdx.x;
    int b  = pp >> 13;
    int hw = (pp << 1) & 16383;
    int h  = hw >> 7;
    int w0 = hw & 127;

    int  offs[9];
    bool ok0[9], ok1[9];
#pragma unroll
    for (int t9 = 0; t9 < 9; t9++) {
        int ty = t9 / 3 - 1, tx = t9 % 3 - 1;
        int yy  = h + ty;
        int xx0 = w0 + tx;
        bool rowok = (unsigned)yy < 128u;
        ok0[t9] = rowok && ((unsigned)xx0 < 128u);
        ok1[t9] = rowok && ((unsigned)(xx0 + 1) < 128u);
        offs[t9] = yy * 128 + xx0;
    }

    unsigned long long acc[28];
#pragma unroll
    for (int m = 0; m < 28; m++) acc[m] = 0ULL;

    const float* xb0 = g_x + (size_t)b * 64 * HW;

#pragma unroll 1
    for (int c = 0; c < 64; c++) {
        const float* xb = xb0 + (size_t)c * HW;
#pragma unroll
        for (int t9 = 0; t9 < 9; t9++) {
            float v0 = ok0[t9] ? xb[offs[t9]]     : 0.0f;
            float v1 = ok1[t9] ? xb[offs[t9] + 1] : 0.0f;
            unsigned long long xp0 = pack2(v0, v0);
            unsigned long long xp1 = pack2(v1, v1);
            const unsigned long long* wrow = s_w + (c * 9 + t9) * 14;
#pragma unroll
            for (int jj = 0; jj < 14; jj += 2) {
                ulonglong2 wv = *(const ulonglong2*)(wrow + jj);
                acc[2 * jj + 0]       = fma2(wv.x, xp0, acc[2 * jj + 0]);
                acc[2 * jj + 1]       = fma2(wv.x, xp1, acc[2 * jj + 1]);
                acc[2 * (jj + 1) + 0] = fma2(wv.y, xp0, acc[2 * (jj + 1) + 0]);
                acc[2 * (jj + 1) + 1] = fma2(wv.y, xp1, acc[2 * (jj + 1) + 1]);
            }
        }
    }

    float e0[28], e1[28];
#pragma unroll
    for (int jj = 0; jj < 14; jj++) {
        float a, bb;
        unpack2(acc[2 * jj + 0], a, bb);  e0[2 * jj] = a;  e0[2 * jj + 1] = bb;
        unpack2(acc[2 * jj + 1], a, bb);  e1[2 * jj] = a;  e1[2 * jj + 1] = bb;
    }

#pragma unroll
    for (int j = 0; j < 18; j++) {
        float bo = b_off[j];
        *(unsigned long long*)(g_off + ((size_t)b * 18 + j) * HW + hw)
            = pack2(e0[j] + bo, e1[j] + bo);
    }
#pragma unroll
    for (int j = 0; j < 9; j++) {
        float bm = b_mod[j];
        float m0 = 2.0f / (1.0f + __expf(-(e0[18 + j] + bm)));
        float m1 = 2.0f / (1.0f + __expf(-(e1[18 + j] + bm)));
        *(unsigned long long*)(g_mod + ((size_t)b * 9 + j) * HW + hw)
            = pack2(m0, m1);
    }
}

// ===========================================================================
// Kernel 3 (mma.sync): per CTA 256-px tile.  Per tap:
//   sample (SIMT, once per px) -> bf16 hi/lo split -> SMEM A[256][72]bf16 x2
//   weights split -> SMEM B[64][72]bf16 x2
//   8 warps: warp w owns px rows w*32..+32, all 64 outs.
//   3-term bf16 HMMA: AhBh + AhBl + AlBh, fp32 reg accumulators across taps.
// Row pitch 144B -> fragment LDS conflict-free ((4*gid+tig) mod 32 perm).
// smem: Ah 36864 + Al 36864 + Bh 9216 + Bl 9216 = 92160B -> 2 CTAs/SM.
// ===========================================================================
#define SA_HI 0
#define SA_LO 36864
#define SB_HI 73728
#define SB_LO 82944
#define K3_SMEM 92160
#define ROWB 144

__global__ void __launch_bounds__(256, 2)
k3_deform(const float* __restrict__ w_reg,
          float* __restrict__ out) {
    extern __shared__ char smem[];
    unsigned sb = smem_u32(smem);
    int tid = threadIdx.x;
    int b       = blockIdx.x >> 6;
    int hw_base = (blockIdx.x & 63) << 8;

    int lane = tid & 31, warp = tid >> 5;
    int gid = lane >> 2, tig = lane & 3;

    // sampling pixel for this thread
    int px = tid;
    int hw = hw_base + px;
    int h  = hw >> 7;
    int w  = hw & 127;

    const float* xb   = g_x   + (size_t)b * 64 * HW;
    const float* offp = g_off + (size_t)b * 18 * HW + hw;
    const float* modp = g_mod + (size_t)b * 9 * HW + hw;

    float d[2][8][4];                                // fp32 accumulators
#pragma unroll
    for (int mt = 0; mt < 2; mt++)
#pragma unroll
        for (int nt = 0; nt < 8; nt++)
#pragma unroll
            for (int e = 0; e < 4; e++) d[mt][nt][e] = 0.0f;

    unsigned arow_hi = sb + SA_HI + px * ROWB;
    unsigned arow_lo = sb + SA_LO + px * ROWB;

#pragma unroll 1
    for (int k = 0; k < 9; k++) {
        __syncthreads();   // previous tap's GEMM reads done before overwrite

        // ---- cooperative weight load + split for tap k ----
#pragma unroll 1
        for (int idx = tid; idx < 2048; idx += 256) {
            int o  = idx >> 5;
            int cp = idx & 31;
            int ch = cp * 2;
            float wa = w_reg[(size_t)o * 576 + ch * 9 + k];
            float wb = w_reg[(size_t)o * 576 + (ch + 1) * 9 + k];
            unsigned hi, lo;
            split_pair(wa, wb, hi, lo);
            sts32(sb + SB_HI + o * ROWB + ch * 2, hi);
            sts32(sb + SB_LO + o * ROWB + ch * 2, lo);
        }

        // ---- sample pixel px for all 64 channels, split + STS ----
        {
            int ky = k / 3, kx = k % 3;
            float dy = offp[(size_t)(2 * k) * HW];
            float dx = offp[(size_t)(2 * k + 1) * HW];
            float mk = modp[(size_t)k * HW];

            float py  = dy + (float)(h - 1 + ky);
            float pxx = dx + (float)(w - 1 + kx);
            float y0f = floorf(py), x0f = floorf(pxx);
            float wy1 = py - y0f, wy0 = 1.0f - wy1;
            float wx1 = pxx - x0f, wx0 = 1.0f - wx1;
            int y0 = (int)y0f, x0 = (int)x0f;
            int y1 = y0 + 1,   x1 = x0 + 1;
            bool vy0 = (unsigned)y0 < 128u, vy1 = (unsigned)y1 < 128u;
            bool vx0 = (unsigned)x0 < 128u, vx1 = (unsigned)x1 < 128u;
            float w00 = (vy0 && vx0) ? wy0 * wx0 * mk : 0.0f;
            float w01 = (vy0 && vx1) ? wy0 * wx1 * mk : 0.0f;
            float w10 = (vy1 && vx0) ? wy1 * wx0 * mk : 0.0f;
            float w11 = (vy1 && vx1) ? wy1 * wx1 * mk : 0.0f;
            int y0c = min(max(y0, 0), 127), y1c = min(max(y1, 0), 127);
            int x0c = min(max(x0, 0), 127), x1c = min(max(x1, 0), 127);
            int a00 = y0c * 128 + x0c;
            int a01 = y0c * 128 + x1c;
            int a10 = y1c * 128 + x0c;
            int a11 = y1c * 128 + x1c;

#pragma unroll 1
            for (int c0 = 0; c0 < 64; c0 += 4) {
                float v[16];
#pragma unroll
                for (int u = 0; u < 4; u++) {
                    const float* pi = xb + (size_t)(c0 + u) * HW;
                    v[4 * u + 0] = pi[a00];
                    v[4 * u + 1] = pi[a01];
                    v[4 * u + 2] = pi[a10];
                    v[4 * u + 3] = pi[a11];
                }
                float s[4];
#pragma unroll
                for (int u = 0; u < 4; u++) {
                    float sv = v[4 * u + 0] * w00;
                    sv = fmaf(v[4 * u + 1], w01, sv);
                    sv = fmaf(v[4 * u + 2], w10, sv);
                    sv = fmaf(v[4 * u + 3], w11, sv);
                    s[u] = sv;
                }
#pragma unroll
                for (int p2 = 0; p2 < 2; p2++) {
                    unsigned hi, lo;
                    split_pair(s[2 * p2], s[2 * p2 + 1], hi, lo);
                    sts32(arow_hi + (c0 + 2 * p2) * 2, hi);
                    sts32(arow_lo + (c0 + 2 * p2) * 2, lo);
                }
            }
        }

        __syncthreads();

        // ---- warp GEMM: 32 px x 64 out, K=64 in 4 k-steps, 3 terms ----
#pragma unroll
        for (int ks = 0; ks < 4; ks++) {
            unsigned kbyte = (unsigned)(ks * 16 + tig * 2) * 2;
            unsigned ahi[2][4], alo[2][4];
#pragma unroll
            for (int mt = 0; mt < 2; mt++) {
                unsigned r0 = warp * 32 + mt * 16 + gid;
                unsigned bh = sb + SA_HI + r0 * ROWB + kbyte;
                unsigned bl = sb + SA_LO + r0 * ROWB + kbyte;
                ahi[mt][0] = lds32(bh);
                ahi[mt][1] = lds32(bh + 8 * ROWB);
                ahi[mt][2] = lds32(bh + 16);
                ahi[mt][3] = lds32(bh + 8 * ROWB + 16);
                alo[mt][0] = lds32(bl);
                alo[mt][1] = lds32(bl + 8 * ROWB);
                alo[mt][2] = lds32(bl + 16);
                alo[mt][3] = lds32(bl + 8 * ROWB + 16);
            }
#pragma unroll
            for (int nt = 0; nt < 8; nt++) {
                unsigned nrow = nt * 8 + gid;
                unsigned bbh = sb + SB_HI + nrow * ROWB + kbyte;
                unsigned bbl = sb + SB_LO + nrow * ROWB + kbyte;
                unsigned bh0 = lds32(bbh), bh1 = lds32(bbh + 16);
                unsigned bl0 = lds32(bbl), bl1 = lds32(bbl + 16);
#pragma unroll
                for (int mt = 0; mt < 2; mt++) {
                    mma16816(d[mt][nt], ahi[mt], bh0, bh1);
                    mma16816(d[mt][nt], ahi[mt], bl0, bl1);
                    mma16816(d[mt][nt], alo[mt], bh0, bh1);
                }
            }
        }
    }

    // ---- epilogue: D fragments -> out ----
#pragma unroll
    for (int mt = 0; mt < 2; mt++) {
#pragma unroll
        for (int nt = 0; nt < 8; nt++) {
            int px0 = warp * 32 + mt * 16 + gid;
            int o0  = nt * 8 + tig * 2;
            float* op = out + ((size_t)b * 64 + o0) * HW + hw_base;
            op[px0]           = d[mt][nt][0];
            op[HW + px0]      = d[mt][nt][1];
            op[px0 + 8]       = d[mt][nt][2];
            op[HW + px0 + 8]  = d[mt][nt][3];
        }
    }
}

// ===========================================================================
extern "C" void kernel_launch(void* const* d_in, const int* in_sizes, int n_in,
                              void* d_out, int out_size) {
    const float* x_img  = (const float*)d_in[0];
    const float* x_cont = (const float*)d_in[1];
    const float* w_fuse = (const float*)d_in[2];
    const float* w_off  = (const float*)d_in[3];
    const float* b_off  = (const float*)d_in[4];
    const float* w_mod  = (const float*)d_in[5];
    const float* b_mod  = (const float*)d_in[6];
    const float* w_reg  = (const float*)d_in[7];
    float* out = (float*)d_out;

    cudaFuncSetAttribute(k2_offmod,
                         cudaFuncAttributeMaxDynamicSharedMemorySize, 64 * 9 * 14 * 8);
    cudaFuncSetAttribute(k3_deform,
                         cudaFuncAttributeMaxDynamicSharedMemorySize, K3_SMEM);

    // k1: 512 blocks x 256 thr
    k1_fuse<<<512, 256, 128 * 64 * 4>>>(x_img, x_cont, w_fuse);
    // k2: 256 blocks x 256 thr
    k2_offmod<<<(NPIX / 2) / 256, 256, 64 * 9 * 14 * 8>>>(w_off, w_mod, b_off, b_mod);
    // k3: 512 blocks x 256 thr; CTA = 256-px tile, mma.sync GEMM
    k3_deform<<<512, 256, K3_SMEM>>>(w_reg, out);
}

// round 12
// speedup vs baseline: 1.4402x; 1.0431x over previous
#include <cuda_runtime.h>
#include <cuda_bf16.h>
#include <math.h>

#define HW   16384
#define NPIX (8 * 16384)

// ---------------- scratch (device globals: no allocation allowed) ----------
__device__ float g_x[8 * 64 * HW];     // fused 1x1 conv output
__device__ float g_off[8 * 18 * HW];   // raw offset conv + bias
__device__ float g_mod[8 * 9 * HW];    // 2*sigmoid(conv + bias)

// ---------------- helpers --------------------------------------------------
__device__ __forceinline__ unsigned smem_u32(const void* p) {
    unsigned a;
    asm("{ .reg .u64 t; cvta.to.shared.u64 t, %1; cvt.u32.u64 %0, t; }"
        : "=r"(a) : "l"(p));
    return a;
}
__device__ __forceinline__ unsigned lds32(unsigned a) {
    unsigned v;
    asm("ld.shared.b32 %0, [%1];" : "=r"(v) : "r"(a));
    return v;
}
__device__ __forceinline__ void sts32(unsigned a, unsigned v) {
    asm volatile("st.shared.b32 [%0], %1;" :: "r"(a), "r"(v) : "memory");
}
__device__ __forceinline__ void mma16816(float* d, const unsigned* a,
                                         unsigned b0, unsigned b1) {
    asm volatile(
        "mma.sync.aligned.m16n8k16.row.col.f32.bf16.bf16.f32 "
        "{%0,%1,%2,%3}, {%4,%5,%6,%7}, {%8,%9}, {%0,%1,%2,%3};"
        : "+f"(d[0]), "+f"(d[1]), "+f"(d[2]), "+f"(d[3])
        : "r"(a[0]), "r"(a[1]), "r"(a[2]), "r"(a[3]), "r"(b0), "r"(b1));
}
// split (a,b) into bf16 hi pair + bf16 lo (residual) pair, packed u32
__device__ __forceinline__ void split_pair(float a, float b,
                                           unsigned& hi, unsigned& lo) {
    __nv_bfloat16 ah = __float2bfloat16(a);
    __nv_bfloat16 bh = __float2bfloat16(b);
    __nv_bfloat16 al = __float2bfloat16(a - __bfloat162float(ah));
    __nv_bfloat16 bl = __float2bfloat16(b - __bfloat162float(bh));
    hi = (unsigned)__bfloat16_as_ushort(ah) | ((unsigned)__bfloat16_as_ushort(bh) << 16);
    lo = (unsigned)__bfloat16_as_ushort(al) | ((unsigned)__bfloat16_as_ushort(bl) << 16);
}

#define ROWB 144

// ===========================================================================
// Kernel 1 (mma.sync): fused 1x1 conv as staged GEMM.
// Per CTA 256-px tile; 2 "taps" = channel halves (x_img, x_cont).
// A[256px][64ch] bf16 hi/lo, B = w_fuse[64out][64ch] hi/lo, 3-term HMMA.
// smem: Ah 36864 + Al 36864 + Bh 9216 + Bl 9216 = 92160B -> 2 CTAs/SM.
// ===========================================================================
#define SA_HI 0
#define SA_LO 36864
#define SB_HI 73728
#define SB_LO 82944
#define K1_SMEM 92160

__global__ void __launch_bounds__(256, 2)
k1_fuse(const float* __restrict__ x_img,
        const float* __restrict__ x_cont,
        const float* __restrict__ w_fuse) {
    extern __shared__ char smem[];
    unsigned sb = smem_u32(smem);
    int tid = threadIdx.x;
    int b       = blockIdx.x >> 6;
    int hw_base = (blockIdx.x & 63) << 8;

    int lane = tid & 31, warp = tid >> 5;
    int gid = lane >> 2, tig = lane & 3;

    int px = tid;
    int hw = hw_base + px;

    float d[2][8][4];
#pragma unroll
    for (int mt = 0; mt < 2; mt++)
#pragma unroll
        for (int nt = 0; nt < 8; nt++)
#pragma unroll
            for (int e = 0; e < 4; e++) d[mt][nt][e] = 0.0f;

    unsigned arow_hi = sb + SA_HI + px * ROWB;
    unsigned arow_lo = sb + SA_LO + px * ROWB;

#pragma unroll 1
    for (int half = 0; half < 2; half++) {
        __syncthreads();

        // ---- weights for this half: w_fuse[o*128 + half*64 + ch] ----
#pragma unroll 1
        for (int idx = tid; idx < 2048; idx += 256) {
            int o  = idx >> 5;
            int cp = idx & 31;
            int ch = cp * 2;
            float wa = w_fuse[o * 128 + half * 64 + ch];
            float wb = w_fuse[o * 128 + half * 64 + ch + 1];
            unsigned hi, lo;
            split_pair(wa, wb, hi, lo);
            sts32(sb + SB_HI + o * ROWB + ch * 2, hi);
            sts32(sb + SB_LO + o * ROWB + ch * 2, lo);
        }

        // ---- input: 64 channels of this pixel, coalesced ----
        const float* xs = (half == 0 ? x_img : x_cont) + (size_t)b * 64 * HW + hw;
#pragma unroll 1
        for (int c0 = 0; c0 < 64; c0 += 8) {
            float v[8];
#pragma unroll
            for (int u = 0; u < 8; u++) v[u] = xs[(size_t)(c0 + u) * HW];
#pragma unroll
            for (int p2 = 0; p2 < 4; p2++) {
                unsigned hi, lo;
                split_pair(v[2 * p2], v[2 * p2 + 1], hi, lo);
                sts32(arow_hi + (c0 + 2 * p2) * 2, hi);
                sts32(arow_lo + (c0 + 2 * p2) * 2, lo);
            }
        }

        __syncthreads();

        // ---- warp GEMM: 32 px x 64 out, K=64, 3 terms ----
#pragma unroll
        for (int ks = 0; ks < 4; ks++) {
            unsigned kbyte = (unsigned)(ks * 16 + tig * 2) * 2;
            unsigned ahi[2][4], alo[2][4];
#pragma unroll
            for (int mt = 0; mt < 2; mt++) {
                unsigned r0 = warp * 32 + mt * 16 + gid;
                unsigned bh = sb + SA_HI + r0 * ROWB + kbyte;
                unsigned bl = sb + SA_LO + r0 * ROWB + kbyte;
                ahi[mt][0] = lds32(bh);
                ahi[mt][1] = lds32(bh + 8 * ROWB);
                ahi[mt][2] = lds32(bh + 16);
                ahi[mt][3] = lds32(bh + 8 * ROWB + 16);
                alo[mt][0] = lds32(bl);
                alo[mt][1] = lds32(bl + 8 * ROWB);
                alo[mt][2] = lds32(bl + 16);
                alo[mt][3] = lds32(bl + 8 * ROWB + 16);
            }
#pragma unroll
            for (int nt = 0; nt < 8; nt++) {
                unsigned nrow = nt * 8 + gid;
                unsigned bbh = sb + SB_HI + nrow * ROWB + kbyte;
                unsigned bbl = sb + SB_LO + nrow * ROWB + kbyte;
                unsigned bh0 = lds32(bbh), bh1 = lds32(bbh + 16);
                unsigned bl0 = lds32(bbl), bl1 = lds32(bbl + 16);
#pragma unroll
                for (int mt = 0; mt < 2; mt++) {
                    mma16816(d[mt][nt], ahi[mt], bh0, bh1);
                    mma16816(d[mt][nt], ahi[mt], bl0, bl1);
                    mma16816(d[mt][nt], alo[mt], bh0, bh1);
                }
            }
        }
    }

    // ---- epilogue -> g_x ----
#pragma unroll
    for (int mt = 0; mt < 2; mt++) {
#pragma unroll
        for (int nt = 0; nt < 8; nt++) {
            int px0 = warp * 32 + mt * 16 + gid;
            int o0  = nt * 8 + tig * 2;
            float* op = g_x + ((size_t)b * 64 + o0) * HW + hw_base;
            op[px0]           = d[mt][nt][0];
            op[HW + px0]      = d[mt][nt][1];
            op[px0 + 8]       = d[mt][nt][2];
            op[HW + px0 + 8]  = d[mt][nt][3];
        }
    }
}

// ===========================================================================
// Kernel 2 (mma.sync): 3x3 conv -> 18 offsets (+bias) and 9 mod
// (bias + 2*sigmoid), as 9-tap staged GEMM with shifted zero-padded reads.
// N = 32 (27 used outs + 5 zero rows of B).
// smem: Ah 36864 + Al 36864 + Bh 4608 + Bl 4608 = 82944B -> 2 CTAs/SM.
// ===========================================================================
#define K2_SB_HI 73728
#define K2_SB_LO 78336
#define K2_SMEM  82944

__global__ void __launch_bounds__(256, 2)
k2_offmod(const float* __restrict__ w_off,
          const float* __restrict__ w_mod,
          const float* __restrict__ b_off,
          const float* __restrict__ b_mod) {
    extern __shared__ char smem[];
    unsigned sb = smem_u32(smem);
    int tid = threadIdx.x;
    int b       = blockIdx.x >> 6;
    int hw_base = (blockIdx.x & 63) << 8;

    int lane = tid & 31, warp = tid >> 5;
    int gid = lane >> 2, tig = lane & 3;

    int px = tid;
    int hw = hw_base + px;
    int h  = hw >> 7;
    int w  = hw & 127;

    const float* xs = g_x + (size_t)b * 64 * HW;

    float d[2][4][4];
#pragma unroll
    for (int mt = 0; mt < 2; mt++)
#pragma unroll
        for (int nt = 0; nt < 4; nt++)
#pragma unroll
            for (int e = 0; e < 4; e++) d[mt][nt][e] = 0.0f;

    unsigned arow_hi = sb + SA_HI + px * ROWB;
    unsigned arow_lo = sb + SA_LO + px * ROWB;

#pragma unroll 1
    for (int k = 0; k < 9; k++) {
        __syncthreads();

        // ---- weights tap k: 32 rows (18 off + 9 mod + 5 zero) ----
#pragma unroll 1
        for (int idx = tid; idx < 1024; idx += 256) {
            int o  = idx >> 5;
            int cp = idx & 31;
            int ch = cp * 2;
            float wa = 0.0f, wb = 0.0f;
            if (o < 18) {
                wa = w_off[((size_t)o * 64 + ch) * 9 + k];
                wb = w_off[((size_t)o * 64 + ch + 1) * 9 + k];
            } else if (o < 27) {
                wa = w_mod[((size_t)(o - 18) * 64 + ch) * 9 + k];
                wb = w_mod[((size_t)(o - 18) * 64 + ch + 1) * 9 + k];
            }
            unsigned hi, lo;
            split_pair(wa, wb, hi, lo);
            sts32(sb + K2_SB_HI + o * ROWB + ch * 2, hi);
            sts32(sb + K2_SB_LO + o * ROWB + ch * 2, lo);
        }

        // ---- shifted zero-padded input read for this pixel ----
        {
            int ty = k / 3 - 1, tx = k % 3 - 1;
            int yy = h + ty, xx = w + tx;
            bool ok = ((unsigned)yy < 128u) && ((unsigned)xx < 128u);
            int addr = ok ? yy * 128 + xx : 0;
#pragma unroll 1
            for (int c0 = 0; c0 < 64; c0 += 8) {
                float v[8];
#pragma unroll
                for (int u = 0; u < 8; u++)
                    v[u] = ok ? xs[(size_t)(c0 + u) * HW + addr] : 0.0f;
#pragma unroll
                for (int p2 = 0; p2 < 4; p2++) {
                    unsigned hi, lo;
                    split_pair(v[2 * p2], v[2 * p2 + 1], hi, lo);
                    sts32(arow_hi + (c0 + 2 * p2) * 2, hi);
                    sts32(arow_lo + (c0 + 2 * p2) * 2, lo);
                }
            }
        }

        __syncthreads();

        // ---- warp GEMM: 32 px x 32 out, K=64, 3 terms ----
#pragma unroll
        for (int ks = 0; ks < 4; ks++) {
            unsigned kbyte = (unsigned)(ks * 16 + tig * 2) * 2;
            unsigned ahi[2][4], alo[2][4];
#pragma unroll
            for (int mt = 0; mt < 2; mt++) {
                unsigned r0 = warp * 32 + mt * 16 + gid;
                unsigned bh = sb + SA_HI + r0 * ROWB + kbyte;
                unsigned bl = sb + SA_LO + r0 * ROWB + kbyte;
                ahi[mt][0] = lds32(bh);
                ahi[mt][1] = lds32(bh + 8 * ROWB);
                ahi[mt][2] = lds32(bh + 16);
                ahi[mt][3] = lds32(bh + 8 * ROWB + 16);
                alo[mt][0] = lds32(bl);
                alo[mt][1] = lds32(bl + 8 * ROWB);
                alo[mt][2] = lds32(bl + 16);
                alo[mt][3] = lds32(bl + 8 * ROWB + 16);
            }
#pragma unroll
            for (int nt = 0; nt < 4; nt++) {
                unsigned nrow = nt * 8 + gid;
                unsigned bbh = sb + K2_SB_HI + nrow * ROWB + kbyte;
                unsigned bbl = sb + K2_SB_LO + nrow * ROWB + kbyte;
                unsigned bh0 = lds32(bbh), bh1 = lds32(bbh + 16);
                unsigned bl0 = lds32(bbl), bl1 = lds32(bbl + 16);
#pragma unroll
                for (int mt = 0; mt < 2; mt++) {
                    mma16816(d[mt][nt], ahi[mt], bh0, bh1);
                    mma16816(d[mt][nt], ahi[mt], bl0, bl1);
                    mma16816(d[mt][nt], alo[mt], bh0, bh1);
                }
            }
        }
    }

    // ---- epilogue: bias / sigmoid, write g_off / g_mod ----
#pragma unroll
    for (int mt = 0; mt < 2; mt++) {
#pragma unroll
        for (int nt = 0; nt < 4; nt++) {
#pragma unroll
            for (int e = 0; e < 4; e++) {
                int o   = nt * 8 + tig * 2 + (e & 1);
                int px0 = warp * 32 + mt * 16 + gid + ((e >> 1) ? 8 : 0);
                float val = d[mt][nt][e];
                if (o < 18) {
                    g_off[((size_t)b * 18 + o) * HW + hw_base + px0]
                        = val + b_off[o];
                } else if (o < 27) {
                    float m = val + b_mod[o - 18];
                    g_mod[((size_t)b * 9 + (o - 18)) * HW + hw_base + px0]
                        = 2.0f / (1.0f + __expf(-m));
                }
            }
        }
    }
}

// ===========================================================================
// Kernel 3 (mma.sync, UNCHANGED from R11 — proven).
// ===========================================================================
#define K3_SB_HI 73728
#define K3_SB_LO 82944
#define K3_SMEM 92160

__global__ void __launch_bounds__(256, 2)
k3_deform(const float* __restrict__ w_reg,
          float* __restrict__ out) {
    extern __shared__ char smem[];
    unsigned sb = smem_u32(smem);
    int tid = threadIdx.x;
    int b       = blockIdx.x >> 6;
    int hw_base = (blockIdx.x & 63) << 8;

    int lane = tid & 31, warp = tid >> 5;
    int gid = lane >> 2, tig = lane & 3;

    int px = tid;
    int hw = hw_base + px;
    int h  = hw >> 7;
    int w  = hw & 127;

    const float* xb   = g_x   + (size_t)b * 64 * HW;
    const float* offp = g_off + (size_t)b * 18 * HW + hw;
    const float* modp = g_mod + (size_t)b * 9 * HW + hw;

    float d[2][8][4];
#pragma unroll
    for (int mt = 0; mt < 2; mt++)
#pragma unroll
        for (int nt = 0; nt < 8; nt++)
#pragma unroll
            for (int e = 0; e < 4; e++) d[mt][nt][e] = 0.0f;

    unsigned arow_hi = sb + SA_HI + px * ROWB;
    unsigned arow_lo = sb + SA_LO + px * ROWB;

#pragma unroll 1
    for (int k = 0; k < 9; k++) {
        __syncthreads();

#pragma unroll 1
        for (int idx = tid; idx < 2048; idx += 256) {
            int o  = idx >> 5;
            int cp = idx & 31;
            int ch = cp * 2;
            float wa = w_reg[(size_t)o * 576 + ch * 9 + k];
            float wb = w_reg[(size_t)o * 576 + (ch + 1) * 9 + k];
            unsigned hi, lo;
            split_pair(wa, wb, hi, lo);
            sts32(sb + K3_SB_HI + o * ROWB + ch * 2, hi);
            sts32(sb + K3_SB_LO + o * ROWB + ch * 2, lo);
        }

        {
            int ky = k / 3, kx = k % 3;
            float dy = offp[(size_t)(2 * k) * HW];
            float dx = offp[(size_t)(2 * k + 1) * HW];
            float mk = modp[(size_t)k * HW];

            float py  = dy + (float)(h - 1 + ky);
            float pxx = dx + (float)(w - 1 + kx);
            float y0f = floorf(py), x0f = floorf(pxx);
            float wy1 = py - y0f, wy0 = 1.0f - wy1;
            float wx1 = pxx - x0f, wx0 = 1.0f - wx1;
            int y0 = (int)y0f, x0 = (int)x0f;
            int y1 = y0 + 1,   x1 = x0 + 1;
            bool vy0 = (unsigned)y0 < 128u, vy1 = (unsigned)y1 < 128u;
            bool vx0 = (unsigned)x0 < 128u, vx1 = (unsigned)x1 < 128u;
            float w00 = (vy0 && vx0) ? wy0 * wx0 * mk : 0.0f;
            float w01 = (vy0 && vx1) ? wy0 * wx1 * mk : 0.0f;
            float w10 = (vy1 && vx0) ? wy1 * wx0 * mk : 0.0f;
            float w11 = (vy1 && vx1) ? wy1 * wx1 * mk : 0.0f;
            int y0c = min(max(y0, 0), 127), y1c = min(max(y1, 0), 127);
            int x0c = min(max(x0, 0), 127), x1c = min(max(x1, 0), 127);
            int a00 = y0c * 128 + x0c;
            int a01 = y0c * 128 + x1c;
            int a10 = y1c * 128 + x0c;
            int a11 = y1c * 128 + x1c;

#pragma unroll 1
            for (int c0 = 0; c0 < 64; c0 += 4) {
                float v[16];
#pragma unroll
                for (int u = 0; u < 4; u++) {
                    const float* pi = xb + (size_t)(c0 + u) * HW;
                    v[4 * u + 0] = pi[a00];
                    v[4 * u + 1] = pi[a01];
                    v[4 * u + 2] = pi[a10];
                    v[4 * u + 3] = pi[a11];
                }
                float s[4];
#pragma unroll
                for (int u = 0; u < 4; u++) {
                    float sv = v[4 * u + 0] * w00;
                    sv = fmaf(v[4 * u + 1], w01, sv);
                    sv = fmaf(v[4 * u + 2], w10, sv);
                    sv = fmaf(v[4 * u + 3], w11, sv);
                    s[u] = sv;
                }
#pragma unroll
                for (int p2 = 0; p2 < 2; p2++) {
                    unsigned hi, lo;
                    split_pair(s[2 * p2], s[2 * p2 + 1], hi, lo);
                    sts32(arow_hi + (c0 + 2 * p2) * 2, hi);
                    sts32(arow_lo + (c0 + 2 * p2) * 2, lo);
                }
            }
        }

        __syncthreads();

#pragma unroll
        for (int ks = 0; ks < 4; ks++) {
            unsigned kbyte = (unsigned)(ks * 16 + tig * 2) * 2;
            unsigned ahi[2][4], alo[2][4];
#pragma unroll
            for (int mt = 0; mt < 2; mt++) {
                unsigned r0 = warp * 32 + mt * 16 + gid;
                unsigned bh = sb + SA_HI + r0 * ROWB + kbyte;
                unsigned bl = sb + SA_LO + r0 * ROWB + kbyte;
                ahi[mt][0] = lds32(bh);
                ahi[mt][1] = lds32(bh + 8 * ROWB);
                ahi[mt][2] = lds32(bh + 16);
                ahi[mt][3] = lds32(bh + 8 * ROWB + 16);
                alo[mt][0] = lds32(bl);
                alo[mt][1] = lds32(bl + 8 * ROWB);
                alo[mt][2] = lds32(bl + 16);
                alo[mt][3] = lds32(bl + 8 * ROWB + 16);
            }
#pragma unroll
            for (int nt = 0; nt < 8; nt++) {
                unsigned nrow = nt * 8 + gid;
                unsigned bbh = sb + K3_SB_HI + nrow * ROWB + kbyte;
                unsigned bbl = sb + K3_SB_LO + nrow * ROWB + kbyte;
                unsigned bh0 = lds32(bbh), bh1 = lds32(bbh + 16);
                unsigned bl0 = lds32(bbl), bl1 = lds32(bbl + 16);
#pragma unroll
                for (int mt = 0; mt < 2; mt++) {
                    mma16816(d[mt][nt], ahi[mt], bh0, bh1);
                    mma16816(d[mt][nt], ahi[mt], bl0, bl1);
                    mma16816(d[mt][nt], alo[mt], bh0, bh1);
                }
            }
        }
    }

#pragma unroll
    for (int mt = 0; mt < 2; mt++) {
#pragma unroll
        for (int nt = 0; nt < 8; nt++) {
            int px0 = warp * 32 + mt * 16 + gid;
            int o0  = nt * 8 + tig * 2;
            float* op = out + ((size_t)b * 64 + o0) * HW + hw_base;
            op[px0]           = d[mt][nt][0];
            op[HW + px0]      = d[mt][nt][1];
            op[px0 + 8]       = d[mt][nt][2];
            op[HW + px0 + 8]  = d[mt][nt][3];
        }
    }
}

// ===========================================================================
extern "C" void kernel_launch(void* const* d_in, const int* in_sizes, int n_in,
                              void* d_out, int out_size) {
    const float* x_img  = (const float*)d_in[0];
    const float* x_cont = (const float*)d_in[1];
    const float* w_fuse = (const float*)d_in[2];
    const float* w_off  = (const float*)d_in[3];
    const float* b_off  = (const float*)d_in[4];
    const float* w_mod  = (const float*)d_in[5];
    const float* b_mod  = (const float*)d_in[6];
    const float* w_reg  = (const float*)d_in[7];
    float* out = (float*)d_out;

    cudaFuncSetAttribute(k1_fuse,
                         cudaFuncAttributeMaxDynamicSharedMemorySize, K1_SMEM);
    cudaFuncSetAttribute(k2_offmod,
                         cudaFuncAttributeMaxDynamicSharedMemorySize, K2_SMEM);
    cudaFuncSetAttribute(k3_deform,
                         cudaFuncAttributeMaxDynamicSharedMemorySize, K3_SMEM);

    // all: 512 blocks x 256 thr; CTA = 256-px tile
    k1_fuse<<<512, 256, K1_SMEM>>>(x_img, x_cont, w_fuse);
    k2_offmod<<<512, 256, K2_SMEM>>>(w_off, w_mod, b_off, b_mod);
    k3_deform<<<512, 256, K3_SMEM>>>(w_reg, out);
}

// round 13
// speedup vs baseline: 1.5946x; 1.1072x over previous
#include <cuda_runtime.h>
#include <cuda_bf16.h>
#include <math.h>

#define HW   16384
#define NPIX (8 * 16384)

// ---------------- scratch (device globals: no allocation allowed) ----------
__device__ float g_x[8 * 64 * HW];     // fused 1x1 conv output
__device__ float g_off[8 * 18 * HW];   // raw offset conv + bias
__device__ float g_mod[8 * 9 * HW];    // 2*sigmoid(conv + bias)

// pre-split weights in smem layout (ROWB=144B pitch, 36 u32/row, pad zeroed)
__device__ unsigned g_wk1[2][2][64 * 36];   // [half][hi/lo][o*36+c]
__device__ unsigned g_wk2[9][2][32 * 36];   // [tap][hi/lo]
__device__ unsigned g_wk3[9][2][64 * 36];   // [tap][hi/lo]

// ---------------- helpers --------------------------------------------------
__device__ __forceinline__ unsigned smem_u32(const void* p) {
    unsigned a;
    asm("{ .reg .u64 t; cvta.to.shared.u64 t, %1; cvt.u32.u64 %0, t; }"
        : "=r"(a) : "l"(p));
    return a;
}
__device__ __forceinline__ unsigned lds32(unsigned a) {
    unsigned v;
    asm("ld.shared.b32 %0, [%1];" : "=r"(v) : "r"(a));
    return v;
}
__device__ __forceinline__ void sts32(unsigned a, unsigned v) {
    asm volatile("st.shared.b32 [%0], %1;" :: "r"(a), "r"(v) : "memory");
}
__device__ __forceinline__ void mma16816(float* d, const unsigned* a,
                                         unsigned b0, unsigned b1) {
    asm volatile(
        "mma.sync.aligned.m16n8k16.row.col.f32.bf16.bf16.f32 "
        "{%0,%1,%2,%3}, {%4,%5,%6,%7}, {%8,%9}, {%0,%1,%2,%3};"
        : "+f"(d[0]), "+f"(d[1]), "+f"(d[2]), "+f"(d[3])
        : "r"(a[0]), "r"(a[1]), "r"(a[2]), "r"(a[3]), "r"(b0), "r"(b1));
}
__device__ __forceinline__ void split_pair(float a, float b,
                                           unsigned& hi, unsigned& lo) {
    __nv_bfloat16 ah = __float2bfloat16(a);
    __nv_bfloat16 bh = __float2bfloat16(b);
    __nv_bfloat16 al = __float2bfloat16(a - __bfloat162float(ah));
    __nv_bfloat16 bl = __float2bfloat16(b - __bfloat162float(bh));
    hi = (unsigned)__bfloat16_as_ushort(ah) | ((unsigned)__bfloat16_as_ushort(bh) << 16);
    lo = (unsigned)__bfloat16_as_ushort(al) | ((unsigned)__bfloat16_as_ushort(bl) << 16);
}

#define ROWB 144

// ===========================================================================
// Setup kernel: pre-split all weights into smem-layout global arrays.
// Runs once per launch (deterministic, graph-capturable, ~5us).
// ===========================================================================
__global__ void ksetup(const float* __restrict__ w_fuse,
                       const float* __restrict__ w_off,
                       const float* __restrict__ w_mod,
                       const float* __restrict__ w_reg) {
    int gtid = blockIdx.x * blockDim.x + threadIdx.x;
    int gsz  = gridDim.x * blockDim.x;

    for (int i = gtid; i < 2 * 64 * 36; i += gsz) {
        int half = i / (64 * 36);
        int r = i % (64 * 36);
        int o = r / 36, c = r % 36;
        unsigned hi = 0, lo = 0;
        if (c < 32) {
            int ch = c * 2;
            split_pair(w_fuse[o * 128 + half * 64 + ch],
                       w_fuse[o * 128 + half * 64 + ch + 1], hi, lo);
        }
        g_wk1[half][0][r] = hi;
        g_wk1[half][1][r] = lo;
    }
    for (int i = gtid; i < 9 * 32 * 36; i += gsz) {
        int k = i / (32 * 36);
        int r = i % (32 * 36);
        int o = r / 36, c = r % 36;
        unsigned hi = 0, lo = 0;
        if (c < 32) {
            int ch = c * 2;
            float wa = 0.0f, wb = 0.0f;
            if (o < 18) {
                wa = w_off[((size_t)o * 64 + ch) * 9 + k];
                wb = w_off[((size_t)o * 64 + ch + 1) * 9 + k];
            } else if (o < 27) {
                wa = w_mod[((size_t)(o - 18) * 64 + ch) * 9 + k];
                wb = w_mod[((size_t)(o - 18) * 64 + ch + 1) * 9 + k];
            }
            split_pair(wa, wb, hi, lo);
        }
        g_wk2[k][0][r] = hi;
        g_wk2[k][1][r] = lo;
    }
    for (int i = gtid; i < 9 * 64 * 36; i += gsz) {
        int k = i / (64 * 36);
        int r = i % (64 * 36);
        int o = r / 36, c = r % 36;
        unsigned hi = 0, lo = 0;
        if (c < 32) {
            int ch = c * 2;
            split_pair(w_reg[(size_t)o * 576 + ch * 9 + k],
                       w_reg[(size_t)o * 576 + (ch + 1) * 9 + k], hi, lo);
        }
        g_wk3[k][0][r] = hi;
        g_wk3[k][1][r] = lo;
    }
}

// ===========================================================================
// Kernel 1 (mma.sync): fused 1x1 conv as staged GEMM.  Weight staging is now
// a coalesced copy from g_wk1.
// ===========================================================================
#define SA_HI 0
#define SA_LO 36864
#define SB_HI 73728
#define SB_LO 82944
#define K1_SMEM 92160

__global__ void __launch_bounds__(256, 2)
k1_fuse(const float* __restrict__ x_img,
        const float* __restrict__ x_cont) {
    extern __shared__ char smem[];
    unsigned sb = smem_u32(smem);
    int tid = threadIdx.x;
    int b       = blockIdx.x >> 6;
    int hw_base = (blockIdx.x & 63) << 8;

    int lane = tid & 31, warp = tid >> 5;
    int gid = lane >> 2, tig = lane & 3;

    int px = tid;
    int hw = hw_base + px;

    float d[2][8][4];
#pragma unroll
    for (int mt = 0; mt < 2; mt++)
#pragma unroll
        for (int nt = 0; nt < 8; nt++)
#pragma unroll
            for (int e = 0; e < 4; e++) d[mt][nt][e] = 0.0f;

    unsigned arow_hi = sb + SA_HI + px * ROWB;
    unsigned arow_lo = sb + SA_LO + px * ROWB;

#pragma unroll 1
    for (int half = 0; half < 2; half++) {
        __syncthreads();

        // ---- weight copy (pre-split, coalesced) ----
        {
            const unsigned* wh = g_wk1[half][0];
            const unsigned* wl = g_wk1[half][1];
#pragma unroll
            for (int idx = tid; idx < 2304; idx += 256) {
                sts32(sb + SB_HI + idx * 4, wh[idx]);
                sts32(sb + SB_LO + idx * 4, wl[idx]);
            }
        }

        // ---- input: 64 channels of this pixel, coalesced ----
        const float* xs = (half == 0 ? x_img : x_cont) + (size_t)b * 64 * HW + hw;
#pragma unroll 1
        for (int c0 = 0; c0 < 64; c0 += 8) {
            float v[8];
#pragma unroll
            for (int u = 0; u < 8; u++) v[u] = xs[(size_t)(c0 + u) * HW];
#pragma unroll
            for (int p2 = 0; p2 < 4; p2++) {
                unsigned hi, lo;
                split_pair(v[2 * p2], v[2 * p2 + 1], hi, lo);
                sts32(arow_hi + (c0 + 2 * p2) * 2, hi);
                sts32(arow_lo + (c0 + 2 * p2) * 2, lo);
            }
        }

        __syncthreads();

        // ---- warp GEMM: 32 px x 64 out, K=64, 3 terms ----
#pragma unroll
        for (int ks = 0; ks < 4; ks++) {
            unsigned kbyte = (unsigned)(ks * 16 + tig * 2) * 2;
            unsigned ahi[2][4], alo[2][4];
#pragma unroll
            for (int mt = 0; mt < 2; mt++) {
                unsigned r0 = warp * 32 + mt * 16 + gid;
                unsigned bh = sb + SA_HI + r0 * ROWB + kbyte;
                unsigned bl = sb + SA_LO + r0 * ROWB + kbyte;
                ahi[mt][0] = lds32(bh);
                ahi[mt][1] = lds32(bh + 8 * ROWB);
                ahi[mt][2] = lds32(bh + 16);
                ahi[mt][3] = lds32(bh + 8 * ROWB + 16);
                alo[mt][0] = lds32(bl);
                alo[mt][1] = lds32(bl + 8 * ROWB);
                alo[mt][2] = lds32(bl + 16);
                alo[mt][3] = lds32(bl + 8 * ROWB + 16);
            }
#pragma unroll
            for (int nt = 0; nt < 8; nt++) {
                unsigned nrow = nt * 8 + gid;
                unsigned bbh = sb + SB_HI + nrow * ROWB + kbyte;
                unsigned bbl = sb + SB_LO + nrow * ROWB + kbyte;
                unsigned bh0 = lds32(bbh), bh1 = lds32(bbh + 16);
                unsigned bl0 = lds32(bbl), bl1 = lds32(bbl + 16);
#pragma unroll
                for (int mt = 0; mt < 2; mt++) {
                    mma16816(d[mt][nt], ahi[mt], bh0, bh1);
                    mma16816(d[mt][nt], ahi[mt], bl0, bl1);
                    mma16816(d[mt][nt], alo[mt], bh0, bh1);
                }
            }
        }
    }

#pragma unroll
    for (int mt = 0; mt < 2; mt++) {
#pragma unroll
        for (int nt = 0; nt < 8; nt++) {
            int px0 = warp * 32 + mt * 16 + gid;
            int o0  = nt * 8 + tig * 2;
            float* op = g_x + ((size_t)b * 64 + o0) * HW + hw_base;
            op[px0]           = d[mt][nt][0];
            op[HW + px0]      = d[mt][nt][1];
            op[px0 + 8]       = d[mt][nt][2];
            op[HW + px0 + 8]  = d[mt][nt][3];
        }
    }
}

// ===========================================================================
// Kernel 2 (mma.sync): 3x3 conv -> offsets/mod.  Weight copy from g_wk2.
// ===========================================================================
#define K2_SB_HI 73728
#define K2_SB_LO 78336
#define K2_SMEM  82944

__global__ void __launch_bounds__(256, 2)
k2_offmod(const float* __restrict__ b_off,
          const float* __restrict__ b_mod) {
    extern __shared__ char smem[];
    unsigned sb = smem_u32(smem);
    int tid = threadIdx.x;
    int b       = blockIdx.x >> 6;
    int hw_base = (blockIdx.x & 63) << 8;

    int lane = tid & 31, warp = tid >> 5;
    int gid = lane >> 2, tig = lane & 3;

    int px = tid;
    int hw = hw_base + px;
    int h  = hw >> 7;
    int w  = hw & 127;

    const float* xs = g_x + (size_t)b * 64 * HW;

    float d[2][4][4];
#pragma unroll
    for (int mt = 0; mt < 2; mt++)
#pragma unroll
        for (int nt = 0; nt < 4; nt++)
#pragma unroll
            for (int e = 0; e < 4; e++) d[mt][nt][e] = 0.0f;

    unsigned arow_hi = sb + SA_HI + px * ROWB;
    unsigned arow_lo = sb + SA_LO + px * ROWB;

#pragma unroll 1
    for (int k = 0; k < 9; k++) {
        __syncthreads();

        // ---- weight copy (pre-split, coalesced) ----
        {
            const unsigned* wh = g_wk2[k][0];
            const unsigned* wl = g_wk2[k][1];
#pragma unroll
            for (int idx = tid; idx < 1152; idx += 256) {
                sts32(sb + K2_SB_HI + idx * 4, wh[idx]);
                sts32(sb + K2_SB_LO + idx * 4, wl[idx]);
            }
        }

        // ---- shifted zero-padded input read ----
        {
            int ty = k / 3 - 1, tx = k % 3 - 1;
            int yy = h + ty, xx = w + tx;
            bool ok = ((unsigned)yy < 128u) && ((unsigned)xx < 128u);
            int addr = ok ? yy * 128 + xx : 0;
#pragma unroll 1
            for (int c0 = 0; c0 < 64; c0 += 8) {
                float v[8];
#pragma unroll
                for (int u = 0; u < 8; u++)
                    v[u] = ok ? xs[(size_t)(c0 + u) * HW + addr] : 0.0f;
#pragma unroll
                for (int p2 = 0; p2 < 4; p2++) {
                    unsigned hi, lo;
                    split_pair(v[2 * p2], v[2 * p2 + 1], hi, lo);
                    sts32(arow_hi + (c0 + 2 * p2) * 2, hi);
                    sts32(arow_lo + (c0 + 2 * p2) * 2, lo);
                }
            }
        }

        __syncthreads();

        // ---- warp GEMM: 32 px x 32 out, K=64, 3 terms ----
#pragma unroll
        for (int ks = 0; ks < 4; ks++) {
            unsigned kbyte = (unsigned)(ks * 16 + tig * 2) * 2;
            unsigned ahi[2][4], alo[2][4];
#pragma unroll
            for (int mt = 0; mt < 2; mt++) {
                unsigned r0 = warp * 32 + mt * 16 + gid;
                unsigned bh = sb + SA_HI + r0 * ROWB + kbyte;
                unsigned bl = sb + SA_LO + r0 * ROWB + kbyte;
                ahi[mt][0] = lds32(bh);
                ahi[mt][1] = lds32(bh + 8 * ROWB);
                ahi[mt][2] = lds32(bh + 16);
                ahi[mt][3] = lds32(bh + 8 * ROWB + 16);
                alo[mt][0] = lds32(bl);
                alo[mt][1] = lds32(bl + 8 * ROWB);
                alo[mt][2] = lds32(bl + 16);
                alo[mt][3] = lds32(bl + 8 * ROWB + 16);
            }
#pragma unroll
            for (int nt = 0; nt < 4; nt++) {
                unsigned nrow = nt * 8 + gid;
                unsigned bbh = sb + K2_SB_HI + nrow * ROWB + kbyte;
                unsigned bbl = sb + K2_SB_LO + nrow * ROWB + kbyte;
                unsigned bh0 = lds32(bbh), bh1 = lds32(bbh + 16);
                unsigned bl0 = lds32(bbl), bl1 = lds32(bbl + 16);
#pragma unroll
                for (int mt = 0; mt < 2; mt++) {
                    mma16816(d[mt][nt], ahi[mt], bh0, bh1);
                    mma16816(d[mt][nt], ahi[mt], bl0, bl1);
                    mma16816(d[mt][nt], alo[mt], bh0, bh1);
                }
            }
        }
    }

    // ---- epilogue: bias / sigmoid ----
#pragma unroll
    for (int mt = 0; mt < 2; mt++) {
#pragma unroll
        for (int nt = 0; nt < 4; nt++) {
#pragma unroll
            for (int e = 0; e < 4; e++) {
                int o   = nt * 8 + tig * 2 + (e & 1);
                int px0 = warp * 32 + mt * 16 + gid + ((e >> 1) ? 8 : 0);
                float val = d[mt][nt][e];
                if (o < 18) {
                    g_off[((size_t)b * 18 + o) * HW + hw_base + px0]
                        = val + b_off[o];
                } else if (o < 27) {
                    float m = val + b_mod[o - 18];
                    g_mod[((size_t)b * 9 + (o - 18)) * HW + hw_base + px0]
                        = 2.0f / (1.0f + __expf(-m));
                }
            }
        }
    }
}

// ===========================================================================
// Kernel 3 (mma.sync): deformable sample + GEMM.  Weight copy from g_wk3,
// next-tap dy/dx/mk prefetch (R5-proven pattern).
// ===========================================================================
#define K3_SB_HI 73728
#define K3_SB_LO 82944
#define K3_SMEM 92160

__global__ void __launch_bounds__(256, 2)
k3_deform(float* __restrict__ out) {
    extern __shared__ char smem[];
    unsigned sb = smem_u32(smem);
    int tid = threadIdx.x;
    int b       = blockIdx.x >> 6;
    int hw_base = (blockIdx.x & 63) << 8;

    int lane = tid & 31, warp = tid >> 5;
    int gid = lane >> 2, tig = lane & 3;

    int px = tid;
    int hw = hw_base + px;
    int h  = hw >> 7;
    int w  = hw & 127;

    const float* xb   = g_x   + (size_t)b * 64 * HW;
    const float* offp = g_off + (size_t)b * 18 * HW + hw;
    const float* modp = g_mod + (size_t)b * 9 * HW + hw;

    float d[2][8][4];
#pragma unroll
    for (int mt = 0; mt < 2; mt++)
#pragma unroll
        for (int nt = 0; nt < 8; nt++)
#pragma unroll
            for (int e = 0; e < 4; e++) d[mt][nt][e] = 0.0f;

    unsigned arow_hi = sb + SA_HI + px * ROWB;
    unsigned arow_lo = sb + SA_LO + px * ROWB;

    float dy = offp[0];
    float dx = offp[(size_t)HW];
    float mk = modp[0];

#pragma unroll 1
    for (int k = 0; k < 9; k++) {
        __syncthreads();

        // ---- weight copy (pre-split, coalesced) ----
        {
            const unsigned* wh = g_wk3[k][0];
            const unsigned* wl = g_wk3[k][1];
#pragma unroll
            for (int idx = tid; idx < 2304; idx += 256) {
                sts32(sb + K3_SB_HI + idx * 4, wh[idx]);
                sts32(sb + K3_SB_LO + idx * 4, wl[idx]);
            }
        }

        // ---- bilinear params (prefetched) + next-tap prefetch ----
        int ky = k / 3, kx = k % 3;
        float py  = dy + (float)(h - 1 + ky);
        float pxx = dx + (float)(w - 1 + kx);
        float y0f = floorf(py), x0f = floorf(pxx);
        float wy1 = py - y0f, wy0 = 1.0f - wy1;
        float wx1 = pxx - x0f, wx0 = 1.0f - wx1;
        int y0 = (int)y0f, x0 = (int)x0f;
        int y1 = y0 + 1,   x1 = x0 + 1;
        bool vy0 = (unsigned)y0 < 128u, vy1 = (unsigned)y1 < 128u;
        bool vx0 = (unsigned)x0 < 128u, vx1 = (unsigned)x1 < 128u;
        float w00 = (vy0 && vx0) ? wy0 * wx0 * mk : 0.0f;
        float w01 = (vy0 && vx1) ? wy0 * wx1 * mk : 0.0f;
        float w10 = (vy1 && vx0) ? wy1 * wx0 * mk : 0.0f;
        float w11 = (vy1 && vx1) ? wy1 * wx1 * mk : 0.0f;
        int y0c = min(max(y0, 0), 127), y1c = min(max(y1, 0), 127);
        int x0c = min(max(x0, 0), 127), x1c = min(max(x1, 0), 127);
        int a00 = y0c * 128 + x0c;
        int a01 = y0c * 128 + x1c;
        int a10 = y1c * 128 + x0c;
        int a11 = y1c * 128 + x1c;

        if (k < 8) {   // prefetch next tap's params (overlaps gathers + GEMM)
            dy = offp[(size_t)(2 * k + 2) * HW];
            dx = offp[(size_t)(2 * k + 3) * HW];
            mk = modp[(size_t)(k + 1) * HW];
        }

        // ---- sample 64 channels, split + STS ----
#pragma unroll 1
        for (int c0 = 0; c0 < 64; c0 += 4) {
            float v[16];
#pragma unroll
            for (int u = 0; u < 4; u++) {
                const float* pi = xb + (size_t)(c0 + u) * HW;
                v[4 * u + 0] = pi[a00];
                v[4 * u + 1] = pi[a01];
                v[4 * u + 2] = pi[a10];
                v[4 * u + 3] = pi[a11];
            }
            float s[4];
#pragma unroll
            for (int u = 0; u < 4; u++) {
                float sv = v[4 * u + 0] * w00;
                sv = fmaf(v[4 * u + 1], w01, sv);
                sv = fmaf(v[4 * u + 2], w10, sv);
                sv = fmaf(v[4 * u + 3], w11, sv);
                s[u] = sv;
            }
#pragma unroll
            for (int p2 = 0; p2 < 2; p2++) {
                unsigned hi, lo;
                split_pair(s[2 * p2], s[2 * p2 + 1], hi, lo);
                sts32(arow_hi + (c0 + 2 * p2) * 2, hi);
                sts32(arow_lo + (c0 + 2 * p2) * 2, lo);
            }
        }

        __syncthreads();

        // ---- warp GEMM: 32 px x 64 out, K=64, 3 terms ----
#pragma unroll
        for (int ks = 0; ks < 4; ks++) {
            unsigned kbyte = (unsigned)(ks * 16 + tig * 2) * 2;
            unsigned ahi[2][4], alo[2][4];
#pragma unroll
            for (int mt = 0; mt < 2; mt++) {
                unsigned r0 = warp * 32 + mt * 16 + gid;
                unsigned bh = sb + SA_HI + r0 * ROWB + kbyte;
                unsigned bl = sb + SA_LO + r0 * ROWB + kbyte;
                ahi[mt][0] = lds32(bh);
                ahi[mt][1] = lds32(bh + 8 * ROWB);
                ahi[mt][2] = lds32(bh + 16);
                ahi[mt][3] = lds32(bh + 8 * ROWB + 16);
                alo[mt][0] = lds32(bl);
                alo[mt][1] = lds32(bl + 8 * ROWB);
                alo[mt][2] = lds32(bl + 16);
                alo[mt][3] = lds32(bl + 8 * ROWB + 16);
            }
#pragma unroll
            for (int nt = 0; nt < 8; nt++) {
                unsigned nrow = nt * 8 + gid;
                unsigned bbh = sb + K3_SB_HI + nrow * ROWB + kbyte;
                unsigned bbl = sb + K3_SB_LO + nrow * ROWB + kbyte;
                unsigned bh0 = lds32(bbh), bh1 = lds32(bbh + 16);
                unsigned bl0 = lds32(bbl), bl1 = lds32(bbl + 16);
#pragma unroll
                for (int mt = 0; mt < 2; mt++) {
                    mma16816(d[mt][nt], ahi[mt], bh0, bh1);
                    mma16816(d[mt][nt], ahi[mt], bl0, bl1);
                    mma16816(d[mt][nt], alo[mt], bh0, bh1);
                }
            }
        }
    }

#pragma unroll
    for (int mt = 0; mt < 2; mt++) {
#pragma unroll
        for (int nt = 0; nt < 8; nt++) {
            int px0 = warp * 32 + mt * 16 + gid;
            int o0  = nt * 8 + tig * 2;
            float* op = out + ((size_t)b * 64 + o0) * HW + hw_base;
            op[px0]           = d[mt][nt][0];
            op[HW + px0]      = d[mt][nt][1];
            op[px0 + 8]       = d[mt][nt][2];
            op[HW + px0 + 8]  = d[mt][nt][3];
        }
    }
}

// ===========================================================================
extern "C" void kernel_launch(void* const* d_in, const int* in_sizes, int n_in,
                              void* d_out, int out_size) {
    const float* x_img  = (const float*)d_in[0];
    const float* x_cont = (const float*)d_in[1];
    const float* w_fuse = (const float*)d_in[2];
    const float* w_off  = (const float*)d_in[3];
    const float* b_off  = (const float*)d_in[4];
    const float* w_mod  = (const float*)d_in[5];
    const float* b_mod  = (const float*)d_in[6];
    const float* w_reg  = (const float*)d_in[7];
    float* out = (float*)d_out;

    cudaFuncSetAttribute(k1_fuse,
                         cudaFuncAttributeMaxDynamicSharedMemorySize, K1_SMEM);
    cudaFuncSetAttribute(k2_offmod,
                         cudaFuncAttributeMaxDynamicSharedMemorySize, K2_SMEM);
    cudaFuncSetAttribute(k3_deform,
                         cudaFuncAttributeMaxDynamicSharedMemorySize, K3_SMEM);

    ksetup<<<128, 256>>>(w_fuse, w_off, w_mod, w_reg);
    k1_fuse<<<512, 256, K1_SMEM>>>(x_img, x_cont);
    k2_offmod<<<512, 256, K2_SMEM>>>(b_off, b_mod);
    k3_deform<<<512, 256, K3_SMEM>>>(out);
}

// round 14
// speedup vs baseline: 1.6672x; 1.0455x over previous
#include <cuda_runtime.h>
#include <cuda_bf16.h>
#include <math.h>

#define HW   16384
#define NPIX (8 * 16384)

// ---------------- scratch (device globals: no allocation allowed) ----------
__device__ float g_x[8 * 64 * HW];     // fused 1x1 conv output
__device__ float g_off[8 * 18 * HW];   // raw offset conv + bias
__device__ float g_mod[8 * 9 * HW];    // 2*sigmoid(conv + bias)

// pre-split weights in smem layout (ROWB=144B pitch, 36 u32/row, pad zeroed)
__device__ unsigned g_wk1[2][2][64 * 36];   // [half][hi/lo][o*36+c]
__device__ unsigned g_wk2[9][2][32 * 36];   // [tap][hi/lo]
__device__ unsigned g_wk3[9][2][64 * 36];   // [tap][hi/lo]

// ---------------- helpers --------------------------------------------------
__device__ __forceinline__ unsigned smem_u32(const void* p) {
    unsigned a;
    asm("{ .reg .u64 t; cvta.to.shared.u64 t, %1; cvt.u32.u64 %0, t; }"
        : "=r"(a) : "l"(p));
    return a;
}
__device__ __forceinline__ unsigned lds32(unsigned a) {
    unsigned v;
    asm("ld.shared.b32 %0, [%1];" : "=r"(v) : "r"(a));
    return v;
}
__device__ __forceinline__ void sts32(unsigned a, unsigned v) {
    asm volatile("st.shared.b32 [%0], %1;" :: "r"(a), "r"(v) : "memory");
}
__device__ __forceinline__ void mma16816(float* d, const unsigned* a,
                                         unsigned b0, unsigned b1) {
    asm volatile(
        "mma.sync.aligned.m16n8k16.row.col.f32.bf16.bf16.f32 "
        "{%0,%1,%2,%3}, {%4,%5,%6,%7}, {%8,%9}, {%0,%1,%2,%3};"
        : "+f"(d[0]), "+f"(d[1]), "+f"(d[2]), "+f"(d[3])
        : "r"(a[0]), "r"(a[1]), "r"(a[2]), "r"(a[3]), "r"(b0), "r"(b1));
}
__device__ __forceinline__ void split_pair(float a, float b,
                                           unsigned& hi, unsigned& lo) {
    __nv_bfloat16 ah = __float2bfloat16(a);
    __nv_bfloat16 bh = __float2bfloat16(b);
    __nv_bfloat16 al = __float2bfloat16(a - __bfloat162float(ah));
    __nv_bfloat16 bl = __float2bfloat16(b - __bfloat162float(bh));
    hi = (unsigned)__bfloat16_as_ushort(ah) | ((unsigned)__bfloat16_as_ushort(bh) << 16);
    lo = (unsigned)__bfloat16_as_ushort(al) | ((unsigned)__bfloat16_as_ushort(bl) << 16);
}

#define ROWB 144

// 128-px tile smem layout
#define SA_HI 0
#define SA_LO 18432
#define SB_HI 36864
#define K1_SB_LO (36864 + 9216)
#define K1_SMEM  (36864 + 18432)      // 55296
#define K2_SB_LO (36864 + 4608)
#define K2_SMEM  (36864 + 9216)       // 46080
#define K3_SB_LO (36864 + 9216)
#define K3_SMEM  (36864 + 18432)      // 55296

// ===========================================================================
// Setup kernel: pre-split all weights into smem-layout global arrays.
// ===========================================================================
__global__ void ksetup(const float* __restrict__ w_fuse,
                       const float* __restrict__ w_off,
                       const float* __restrict__ w_mod,
                       const float* __restrict__ w_reg) {
    int gtid = blockIdx.x * blockDim.x + threadIdx.x;
    int gsz  = gridDim.x * blockDim.x;

    for (int i = gtid; i < 2 * 64 * 36; i += gsz) {
        int half = i / (64 * 36);
        int r = i % (64 * 36);
        int o = r / 36, c = r % 36;
        unsigned hi = 0, lo = 0;
        if (c < 32) {
            int ch = c * 2;
            split_pair(w_fuse[o * 128 + half * 64 + ch],
                       w_fuse[o * 128 + half * 64 + ch + 1], hi, lo);
        }
        g_wk1[half][0][r] = hi;
        g_wk1[half][1][r] = lo;
    }
    for (int i = gtid; i < 9 * 32 * 36; i += gsz) {
        int k = i / (32 * 36);
        int r = i % (32 * 36);
        int o = r / 36, c = r % 36;
        unsigned hi = 0, lo = 0;
        if (c < 32) {
            int ch = c * 2;
            float wa = 0.0f, wb = 0.0f;
            if (o < 18) {
                wa = w_off[((size_t)o * 64 + ch) * 9 + k];
                wb = w_off[((size_t)o * 64 + ch + 1) * 9 + k];
            } else if (o < 27) {
                wa = w_mod[((size_t)(o - 18) * 64 + ch) * 9 + k];
                wb = w_mod[((size_t)(o - 18) * 64 + ch + 1) * 9 + k];
            }
            split_pair(wa, wb, hi, lo);
        }
        g_wk2[k][0][r] = hi;
        g_wk2[k][1][r] = lo;
    }
    for (int i = gtid; i < 9 * 64 * 36; i += gsz) {
        int k = i / (64 * 36);
        int r = i % (64 * 36);
        int o = r / 36, c = r % 36;
        unsigned hi = 0, lo = 0;
        if (c < 32) {
            int ch = c * 2;
            split_pair(w_reg[(size_t)o * 576 + ch * 9 + k],
                       w_reg[(size_t)o * 576 + (ch + 1) * 9 + k], hi, lo);
        }
        g_wk3[k][0][r] = hi;
        g_wk3[k][1][r] = lo;
    }
}

// ===========================================================================
// Kernel 1 (mma.sync): fused 1x1 conv.  128-px tile, 128 thr, 4 CTAs/SM.
// ===========================================================================
__global__ void __launch_bounds__(128, 4)
k1_fuse(const float* __restrict__ x_img,
        const float* __restrict__ x_cont) {
    extern __shared__ char smem[];
    unsigned sb = smem_u32(smem);
    int tid = threadIdx.x;
    int b       = blockIdx.x >> 7;
    int hw_base = (blockIdx.x & 127) << 7;

    int lane = tid & 31, warp = tid >> 5;
    int gid = lane >> 2, tig = lane & 3;

    int px = tid;
    int hw = hw_base + px;

    float d[2][8][4];
#pragma unroll
    for (int mt = 0; mt < 2; mt++)
#pragma unroll
        for (int nt = 0; nt < 8; nt++)
#pragma unroll
            for (int e = 0; e < 4; e++) d[mt][nt][e] = 0.0f;

    unsigned arow_hi = sb + SA_HI + px * ROWB;
    unsigned arow_lo = sb + SA_LO + px * ROWB;

#pragma unroll 1
    for (int half = 0; half < 2; half++) {
        __syncthreads();

        // ---- weight copy (pre-split, coalesced) ----
        {
            const unsigned* wh = g_wk1[half][0];
            const unsigned* wl = g_wk1[half][1];
#pragma unroll
            for (int idx = tid; idx < 2304; idx += 128) {
                sts32(sb + SB_HI + idx * 4, wh[idx]);
                sts32(sb + K1_SB_LO + idx * 4, wl[idx]);
            }
        }

        // ---- input: 64 channels of this pixel, coalesced ----
        const float* xs = (half == 0 ? x_img : x_cont) + (size_t)b * 64 * HW + hw;
#pragma unroll 1
        for (int c0 = 0; c0 < 64; c0 += 8) {
            float v[8];
#pragma unroll
            for (int u = 0; u < 8; u++) v[u] = xs[(size_t)(c0 + u) * HW];
#pragma unroll
            for (int p2 = 0; p2 < 4; p2++) {
                unsigned hi, lo;
                split_pair(v[2 * p2], v[2 * p2 + 1], hi, lo);
                sts32(arow_hi + (c0 + 2 * p2) * 2, hi);
                sts32(arow_lo + (c0 + 2 * p2) * 2, lo);
            }
        }

        __syncthreads();

        // ---- warp GEMM: 32 px x 64 out, K=64, 3 terms ----
#pragma unroll
        for (int ks = 0; ks < 4; ks++) {
            unsigned kbyte = (unsigned)(ks * 16 + tig * 2) * 2;
            unsigned ahi[2][4], alo[2][4];
#pragma unroll
            for (int mt = 0; mt < 2; mt++) {
                unsigned r0 = warp * 32 + mt * 16 + gid;
                unsigned bh = sb + SA_HI + r0 * ROWB + kbyte;
                unsigned bl = sb + SA_LO + r0 * ROWB + kbyte;
                ahi[mt][0] = lds32(bh);
                ahi[mt][1] = lds32(bh + 8 * ROWB);
                ahi[mt][2] = lds32(bh + 16);
                ahi[mt][3] = lds32(bh + 8 * ROWB + 16);
                alo[mt][0] = lds32(bl);
                alo[mt][1] = lds32(bl + 8 * ROWB);
                alo[mt][2] = lds32(bl + 16);
                alo[mt][3] = lds32(bl + 8 * ROWB + 16);
            }
#pragma unroll
            for (int nt = 0; nt < 8; nt++) {
                unsigned nrow = nt * 8 + gid;
                unsigned bbh = sb + SB_HI + nrow * ROWB + kbyte;
                unsigned bbl = sb + K1_SB_LO + nrow * ROWB + kbyte;
                unsigned bh0 = lds32(bbh), bh1 = lds32(bbh + 16);
                unsigned bl0 = lds32(bbl), bl1 = lds32(bbl + 16);
#pragma unroll
                for (int mt = 0; mt < 2; mt++) {
                    mma16816(d[mt][nt], ahi[mt], bh0, bh1);
                    mma16816(d[mt][nt], ahi[mt], bl0, bl1);
                    mma16816(d[mt][nt], alo[mt], bh0, bh1);
                }
            }
        }
    }

#pragma unroll
    for (int mt = 0; mt < 2; mt++) {
#pragma unroll
        for (int nt = 0; nt < 8; nt++) {
            int px0 = warp * 32 + mt * 16 + gid;
            int o0  = nt * 8 + tig * 2;
            float* op = g_x + ((size_t)b * 64 + o0) * HW + hw_base;
            op[px0]           = d[mt][nt][0];
            op[HW + px0]      = d[mt][nt][1];
            op[px0 + 8]       = d[mt][nt][2];
            op[HW + px0 + 8]  = d[mt][nt][3];
        }
    }
}

// ===========================================================================
// Kernel 2 (mma.sync): 3x3 conv -> offsets/mod.  128-px tile, 4 CTAs/SM.
// ===========================================================================
__global__ void __launch_bounds__(128, 4)
k2_offmod(const float* __restrict__ b_off,
          const float* __restrict__ b_mod) {
    extern __shared__ char smem[];
    unsigned sb = smem_u32(smem);
    int tid = threadIdx.x;
    int b       = blockIdx.x >> 7;
    int hw_base = (blockIdx.x & 127) << 7;

    int lane = tid & 31, warp = tid >> 5;
    int gid = lane >> 2, tig = lane & 3;

    int px = tid;
    int hw = hw_base + px;
    int h  = hw >> 7;
    int w  = hw & 127;

    const float* xs = g_x + (size_t)b * 64 * HW;

    float d[2][4][4];
#pragma unroll
    for (int mt = 0; mt < 2; mt++)
#pragma unroll
        for (int nt = 0; nt < 4; nt++)
#pragma unroll
            for (int e = 0; e < 4; e++) d[mt][nt][e] = 0.0f;

    unsigned arow_hi = sb + SA_HI + px * ROWB;
    unsigned arow_lo = sb + SA_LO + px * ROWB;

#pragma unroll 1
    for (int k = 0; k < 9; k++) {
        __syncthreads();

        // ---- weight copy ----
        {
            const unsigned* wh = g_wk2[k][0];
            const unsigned* wl = g_wk2[k][1];
#pragma unroll
            for (int idx = tid; idx < 1152; idx += 128) {
                sts32(sb + SB_HI + idx * 4, wh[idx]);
                sts32(sb + K2_SB_LO + idx * 4, wl[idx]);
            }
        }

        // ---- shifted zero-padded input read ----
        {
            int ty = k / 3 - 1, tx = k % 3 - 1;
            int yy = h + ty, xx = w + tx;
            bool ok = ((unsigned)yy < 128u) && ((unsigned)xx < 128u);
            int addr = ok ? yy * 128 + xx : 0;
#pragma unroll 1
            for (int c0 = 0; c0 < 64; c0 += 8) {
                float v[8];
#pragma unroll
                for (int u = 0; u < 8; u++)
                    v[u] = ok ? xs[(size_t)(c0 + u) * HW + addr] : 0.0f;
#pragma unroll
                for (int p2 = 0; p2 < 4; p2++) {
                    unsigned hi, lo;
                    split_pair(v[2 * p2], v[2 * p2 + 1], hi, lo);
                    sts32(arow_hi + (c0 + 2 * p2) * 2, hi);
                    sts32(arow_lo + (c0 + 2 * p2) * 2, lo);
                }
            }
        }

        __syncthreads();

        // ---- warp GEMM: 32 px x 32 out, K=64, 3 terms ----
#pragma unroll
        for (int ks = 0; ks < 4; ks++) {
            unsigned kbyte = (unsigned)(ks * 16 + tig * 2) * 2;
            unsigned ahi[2][4], alo[2][4];
#pragma unroll
            for (int mt = 0; mt < 2; mt++) {
                unsigned r0 = warp * 32 + mt * 16 + gid;
                unsigned bh = sb + SA_HI + r0 * ROWB + kbyte;
                unsigned bl = sb + SA_LO + r0 * ROWB + kbyte;
                ahi[mt][0] = lds32(bh);
                ahi[mt][1] = lds32(bh + 8 * ROWB);
                ahi[mt][2] = lds32(bh + 16);
                ahi[mt][3] = lds32(bh + 8 * ROWB + 16);
                alo[mt][0] = lds32(bl);
                alo[mt][1] = lds32(bl + 8 * ROWB);
                alo[mt][2] = lds32(bl + 16);
                alo[mt][3] = lds32(bl + 8 * ROWB + 16);
            }
#pragma unroll
            for (int nt = 0; nt < 4; nt++) {
                unsigned nrow = nt * 8 + gid;
                unsigned bbh = sb + SB_HI + nrow * ROWB + kbyte;
                unsigned bbl = sb + K2_SB_LO + nrow * ROWB + kbyte;
                unsigned bh0 = lds32(bbh), bh1 = lds32(bbh + 16);
                unsigned bl0 = lds32(bbl), bl1 = lds32(bbl + 16);
#pragma unroll
                for (int mt = 0; mt < 2; mt++) {
                    mma16816(d[mt][nt], ahi[mt], bh0, bh1);
                    mma16816(d[mt][nt], ahi[mt], bl0, bl1);
                    mma16816(d[mt][nt], alo[mt], bh0, bh1);
                }
            }
        }
    }

    // ---- epilogue: bias / sigmoid ----
#pragma unroll
    for (int mt = 0; mt < 2; mt++) {
#pragma unroll
        for (int nt = 0; nt < 4; nt++) {
#pragma unroll
            for (int e = 0; e < 4; e++) {
                int o   = nt * 8 + tig * 2 + (e & 1);
                int px0 = warp * 32 + mt * 16 + gid + ((e >> 1) ? 8 : 0);
                float val = d[mt][nt][e];
                if (o < 18) {
                    g_off[((size_t)b * 18 + o) * HW + hw_base + px0]
                        = val + b_off[o];
                } else if (o < 27) {
                    float m = val + b_mod[o - 18];
                    g_mod[((size_t)b * 9 + (o - 18)) * HW + hw_base + px0]
                        = 2.0f / (1.0f + __expf(-m));
                }
            }
        }
    }
}

// ===========================================================================
// Kernel 3 (mma.sync): deformable sample + GEMM.  128-px tile, 4 CTAs/SM.
// ===========================================================================
__global__ void __launch_bounds__(128, 4)
k3_deform(float* __restrict__ out) {
    extern __shared__ char smem[];
    unsigned sb = smem_u32(smem);
    int tid = threadIdx.x;
    int b       = blockIdx.x >> 7;
    int hw_base = (blockIdx.x & 127) << 7;

    int lane = tid & 31, warp = tid >> 5;
    int gid = lane >> 2, tig = lane & 3;

    int px = tid;
    int hw = hw_base + px;
    int h  = hw >> 7;
    int w  = hw & 127;

    const float* xb   = g_x   + (size_t)b * 64 * HW;
    const float* offp = g_off + (size_t)b * 18 * HW + hw;
    const float* modp = g_mod + (size_t)b * 9 * HW + hw;

    float d[2][8][4];
#pragma unroll
    for (int mt = 0; mt < 2; mt++)
#pragma unroll
        for (int nt = 0; nt < 8; nt++)
#pragma unroll
            for (int e = 0; e < 4; e++) d[mt][nt][e] = 0.0f;

    unsigned arow_hi = sb + SA_HI + px * ROWB;
    unsigned arow_lo = sb + SA_LO + px * ROWB;

    float dy = offp[0];
    float dx = offp[(size_t)HW];
    float mk = modp[0];

#pragma unroll 1
    for (int k = 0; k < 9; k++) {
        __syncthreads();

        // ---- weight copy ----
        {
            const unsigned* wh = g_wk3[k][0];
            const unsigned* wl = g_wk3[k][1];
#pragma unroll
            for (int idx = tid; idx < 2304; idx += 128) {
                sts32(sb + SB_HI + idx * 4, wh[idx]);
                sts32(sb + K3_SB_LO + idx * 4, wl[idx]);
            }
        }

        // ---- bilinear params (prefetched) + next-tap prefetch ----
        int ky = k / 3, kx = k % 3;
        float py  = dy + (float)(h - 1 + ky);
        float pxx = dx + (float)(w - 1 + kx);
        float y0f = floorf(py), x0f = floorf(pxx);
        float wy1 = py - y0f, wy0 = 1.0f - wy1;
        float wx1 = pxx - x0f, wx0 = 1.0f - wx1;
        int y0 = (int)y0f, x0 = (int)x0f;
        int y1 = y0 + 1,   x1 = x0 + 1;
        bool vy0 = (unsigned)y0 < 128u, vy1 = (unsigned)y1 < 128u;
        bool vx0 = (unsigned)x0 < 128u, vx1 = (unsigned)x1 < 128u;
        float w00 = (vy0 && vx0) ? wy0 * wx0 * mk : 0.0f;
        float w01 = (vy0 && vx1) ? wy0 * wx1 * mk : 0.0f;
        float w10 = (vy1 && vx0) ? wy1 * wx0 * mk : 0.0f;
        float w11 = (vy1 && vx1) ? wy1 * wx1 * mk : 0.0f;
        int y0c = min(max(y0, 0), 127), y1c = min(max(y1, 0), 127);
        int x0c = min(max(x0, 0), 127), x1c = min(max(x1, 0), 127);
        int a00 = y0c * 128 + x0c;
        int a01 = y0c * 128 + x1c;
        int a10 = y1c * 128 + x0c;
        int a11 = y1c * 128 + x1c;

        if (k < 8) {
            dy = offp[(size_t)(2 * k + 2) * HW];
            dx = offp[(size_t)(2 * k + 3) * HW];
            mk = modp[(size_t)(k + 1) * HW];
        }

        // ---- sample 64 channels, split + STS ----
#pragma unroll 1
        for (int c0 = 0; c0 < 64; c0 += 4) {
            float v[16];
#pragma unroll
            for (int u = 0; u < 4; u++) {
                const float* pi = xb + (size_t)(c0 + u) * HW;
                v[4 * u + 0] = pi[a00];
                v[4 * u + 1] = pi[a01];
                v[4 * u + 2] = pi[a10];
                v[4 * u + 3] = pi[a11];
            }
            float s[4];
#pragma unroll
            for (int u = 0; u < 4; u++) {
                float sv = v[4 * u + 0] * w00;
                sv = fmaf(v[4 * u + 1], w01, sv);
                sv = fmaf(v[4 * u + 2], w10, sv);
                sv = fmaf(v[4 * u + 3], w11, sv);
                s[u] = sv;
            }
#pragma unroll
            for (int p2 = 0; p2 < 2; p2++) {
                unsigned hi, lo;
                split_pair(s[2 * p2], s[2 * p2 + 1], hi, lo);
                sts32(arow_hi + (c0 + 2 * p2) * 2, hi);
                sts32(arow_lo + (c0 + 2 * p2) * 2, lo);
            }
        }

        __syncthreads();

        // ---- warp GEMM: 32 px x 64 out, K=64, 3 terms ----
#pragma unroll
        for (int ks = 0; ks < 4; ks++) {
            unsigned kbyte = (unsigned)(ks * 16 + tig * 2) * 2;
            unsigned ahi[2][4], alo[2][4];
#pragma unroll
            for (int mt = 0; mt < 2; mt++) {
                unsigned r0 = warp * 32 + mt * 16 + gid;
                unsigned bh = sb + SA_HI + r0 * ROWB + kbyte;
                unsigned bl = sb + SA_LO + r0 * ROWB + kbyte;
                ahi[mt][0] = lds32(bh);
                ahi[mt][1] = lds32(bh + 8 * ROWB);
                ahi[mt][2] = lds32(bh + 16);
                ahi[mt][3] = lds32(bh + 8 * ROWB + 16);
                alo[mt][0] = lds32(bl);
                alo[mt][1] = lds32(bl + 8 * ROWB);
                alo[mt][2] = lds32(bl + 16);
                alo[mt][3] = lds32(bl + 8 * ROWB + 16);
            }
#pragma unroll
            for (int nt = 0; nt < 8; nt++) {
                unsigned nrow = nt * 8 + gid;
                unsigned bbh = sb + SB_HI + nrow * ROWB + kbyte;
                unsigned bbl = sb + K3_SB_LO + nrow * ROWB + kbyte;
                unsigned bh0 = lds32(bbh), bh1 = lds32(bbh + 16);
                unsigned bl0 = lds32(bbl), bl1 = lds32(bbl + 16);
#pragma unroll
                for (int mt = 0; mt < 2; mt++) {
                    mma16816(d[mt][nt], ahi[mt], bh0, bh1);
                    mma16816(d[mt][nt], ahi[mt], bl0, bl1);
                    mma16816(d[mt][nt], alo[mt], bh0, bh1);
                }
            }
        }
    }

#pragma unroll
    for (int mt = 0; mt < 2; mt++) {
#pragma unroll
        for (int nt = 0; nt < 8; nt++) {
            int px0 = warp * 32 + mt * 16 + gid;
            int o0  = nt * 8 + tig * 2;
            float* op = out + ((size_t)b * 64 + o0) * HW + hw_base;
            op[px0]           = d[mt][nt][0];
            op[HW + px0]      = d[mt][nt][1];
            op[px0 + 8]       = d[mt][nt][2];
            op[HW + px0 + 8]  = d[mt][nt][3];
        }
    }
}

// ===========================================================================
extern "C" void kernel_launch(void* const* d_in, const int* in_sizes, int n_in,
                              void* d_out, int out_size) {
    const float* x_img  = (const float*)d_in[0];
    const float* x_cont = (const float*)d_in[1];
    const float* w_fuse = (const float*)d_in[2];
    const float* w_off  = (const float*)d_in[3];
    const float* b_off  = (const float*)d_in[4];
    const float* w_mod  = (const float*)d_in[5];
    const float* b_mod  = (const float*)d_in[6];
    const float* w_reg  = (const float*)d_in[7];
    float* out = (float*)d_out;

    cudaFuncSetAttribute(k1_fuse,
                         cudaFuncAttributeMaxDynamicSharedMemorySize, K1_SMEM);
    cudaFuncSetAttribute(k2_offmod,
                         cudaFuncAttributeMaxDynamicSharedMemorySize, K2_SMEM);
    cudaFuncSetAttribute(k3_deform,
                         cudaFuncAttributeMaxDynamicSharedMemorySize, K3_SMEM);

    ksetup<<<128, 256>>>(w_fuse, w_off, w_mod, w_reg);
    // all: 1024 blocks x 128 thr; CTA = 128-px tile
    k1_fuse<<<1024, 128, K1_SMEM>>>(x_img, x_cont);
    k2_offmod<<<1024, 128, K2_SMEM>>>(b_off, b_mod);
    k3_deform<<<1024, 128, K3_SMEM>>>(out);
}